// round 1
// baseline (speedup 1.0000x reference)
#include <cuda_runtime.h>
#include <mma.h>
#include <math.h>

using namespace nvcuda;

// ---------------- problem constants ----------------
#define BB 64
#define SS 168
#define F_IN 10
#define DD 512
#define HH 8
#define LL 4
#define HID 2048
#define NFUT 48
#define DH (DD*HH)          // 4096
#define MTOK (BB*SS)        // 10752

// ---------------- scratch (static device globals; no allocations) ----------------
__device__ float g_h  [MTOK*DD];      // residual stream
__device__ float g_h1 [MTOK*DD];      // post-attn LN
__device__ float g_t  [MTOK*DD];      // dn / mo output
__device__ float g_q  [MTOK*DH];      // Q, then reused as attention context output
__device__ float g_k  [MTOK*DH];
__device__ float g_v  [MTOK*DH];
__device__ float g_s  [BB*HH*SS*SS];  // scores / probs
__device__ float g_mlp[MTOK*HID];

// ---------------- generic strided-batched TF32 GEMM ----------------
// C[M,N] = alpha * A[M,K] @ (B or B^T) (+bias[n]) (+relu)
// batch z: b=z/Hs, h=z%Hs; each operand offset by b*s?b + h*s?h.
#define TM 128
#define TN 128
#define TK 32
#define LDA_S 40   // 32B-aligned strides for wmma (multiples of 8 floats)
#define LDB_S 136
#define FLAG_RELU 1
#define FLAG_TRB  2
#define FLAG_BIAS 4

__global__ void __launch_bounds__(256)
gemm_tf32(const float* __restrict__ A, const float* __restrict__ Bm,
          const float* __restrict__ bias, float* __restrict__ C,
          int M, int N, int K, int lda, int ldb, int ldc,
          long long sAb, long long sAh, long long sBb, long long sBh,
          long long sCb, long long sCh, int Hs,
          float alpha, int flags)
{
    int z = blockIdx.z;
    int b = z / Hs, hh = z % Hs;
    A  += (long long)b * sAb + (long long)hh * sAh;
    Bm += (long long)b * sBb + (long long)hh * sBh;
    C  += (long long)b * sCb + (long long)hh * sCh;

    __shared__ __align__(32) float As[TM][LDA_S];
    __shared__ __align__(32) float Bs[TK][LDB_S];
    __shared__ __align__(32) float Cs[8][16][16];

    const int tile_m = blockIdx.y * TM;
    const int tile_n = blockIdx.x * TN;
    const int tid  = threadIdx.x;
    const int warp = tid >> 5;
    const int lane = tid & 31;
    const int wm = warp & 3;   // 4 warps along M (32 rows each)
    const int wn = warp >> 2;  // 2 warps along N (64 cols each)

    wmma::fragment<wmma::accumulator, 16, 16, 8, float> cf[2][4];
    #pragma unroll
    for (int i = 0; i < 2; i++)
        #pragma unroll
        for (int j = 0; j < 4; j++)
            wmma::fill_fragment(cf[i][j], 0.0f);

    const bool trb = (flags & FLAG_TRB) != 0;

    for (int k0 = 0; k0 < K; k0 += TK) {
        // stage A (TM x TK), bounds-checked, convert to tf32 once
        #pragma unroll
        for (int i = tid; i < TM * TK; i += 256) {
            int r = i >> 5, c = i & 31;           // TK==32
            int gm = tile_m + r, gk = k0 + c;
            float v = (gm < M && gk < K) ? A[(long long)gm * lda + gk] : 0.0f;
            As[r][c] = wmma::__float_to_tf32(v);
        }
        // stage B (TK x TN)
        if (!trb) {
            #pragma unroll
            for (int i = tid; i < TK * TN; i += 256) {
                int r = i >> 7, c = i & 127;      // TN==128
                int gk = k0 + r, gn = tile_n + c;
                float v = (gk < K && gn < N) ? Bm[(long long)gk * ldb + gn] : 0.0f;
                Bs[r][c] = wmma::__float_to_tf32(v);
            }
        } else {
            #pragma unroll
            for (int i = tid; i < TK * TN; i += 256) {
                int c = i >> 5, r = i & 31;       // c = n, r = k (coalesced on k)
                int gk = k0 + r, gn = tile_n + c;
                float v = (gk < K && gn < N) ? Bm[(long long)gn * ldb + gk] : 0.0f;
                Bs[r][c] = wmma::__float_to_tf32(v);
            }
        }
        __syncthreads();

        #pragma unroll
        for (int kk = 0; kk < TK; kk += 8) {
            wmma::fragment<wmma::matrix_a, 16, 16, 8, wmma::precision::tf32, wmma::row_major> af[2];
            wmma::fragment<wmma::matrix_b, 16, 16, 8, wmma::precision::tf32, wmma::row_major> bf[4];
            #pragma unroll
            for (int mi = 0; mi < 2; mi++)
                wmma::load_matrix_sync(af[mi], &As[wm * 32 + mi * 16][kk], LDA_S);
            #pragma unroll
            for (int ni = 0; ni < 4; ni++)
                wmma::load_matrix_sync(bf[ni], &Bs[kk][wn * 64 + ni * 16], LDB_S);
            #pragma unroll
            for (int mi = 0; mi < 2; mi++)
                #pragma unroll
                for (int ni = 0; ni < 4; ni++)
                    wmma::mma_sync(cf[mi][ni], af[mi], bf[ni], cf[mi][ni]);
        }
        __syncthreads();
    }

    // epilogue via per-warp smem staging (handles ragged M,N)
    #pragma unroll
    for (int mi = 0; mi < 2; mi++) {
        #pragma unroll
        for (int ni = 0; ni < 4; ni++) {
            wmma::store_matrix_sync(&Cs[warp][0][0], cf[mi][ni], 16, wmma::mem_row_major);
            __syncwarp();
            #pragma unroll
            for (int e = lane; e < 256; e += 32) {
                int rr = e >> 4, cc = e & 15;
                int gm = tile_m + wm * 32 + mi * 16 + rr;
                int gn = tile_n + wn * 64 + ni * 16 + cc;
                if (gm < M && gn < N) {
                    float v = Cs[warp][rr][cc] * alpha;
                    if (flags & FLAG_BIAS) v += bias[gn];
                    if (flags & FLAG_RELU) v = fmaxf(v, 0.0f);
                    C[(long long)gm * ldc + gn] = v;
                }
            }
            __syncwarp();
        }
    }
}

// ---------------- embedding: h = (x @ in_w + in_b) * sqrt(D) + PE ----------------
__global__ void embed_kernel(const float* __restrict__ x, const float* __restrict__ w,
                             const float* __restrict__ b, float* __restrict__ h)
{
    int idx = blockIdx.x * 256 + threadIdx.x;
    if (idx >= MTOK * DD) return;
    int row = idx / DD, d = idx % DD;
    int s = row % SS;
    const float* xr = x + row * F_IN;
    float acc = b[d];
    #pragma unroll
    for (int f = 0; f < F_IN; f++) acc += xr[f] * w[f * DD + d];
    acc *= 22.627416997969522f; // sqrt(512)
    float di2 = (float)(2 * (d >> 1));
    // angle = s / 10000^(di2/512) = s * exp(-ln(10000)*di2/512)
    float ang = (float)s * expf(di2 * (-9.210340371976184f / (float)DD));
    float pe = (d & 1) ? cosf(ang) : sinf(ang);
    h[idx] = acc + pe;
}

// ---------------- causal softmax over score rows ----------------
__global__ void softmax_kernel(float* __restrict__ s)
{
    int row = blockIdx.x * 8 + (threadIdx.x >> 5); // one warp per row
    if (row >= BB * HH * SS) return;
    int lane = threadIdx.x & 31;
    int q = row % SS;
    float* p = s + (long long)row * SS;

    float m = -1e30f;
    for (int j = lane; j <= q; j += 32) m = fmaxf(m, p[j]);
    #pragma unroll
    for (int o = 16; o; o >>= 1) m = fmaxf(m, __shfl_xor_sync(0xffffffffu, m, o));

    float sum = 0.0f;
    for (int j = lane; j <= q; j += 32) sum += expf(p[j] - m);
    #pragma unroll
    for (int o = 16; o; o >>= 1) sum += __shfl_xor_sync(0xffffffffu, sum, o);
    float inv = 1.0f / sum;

    for (int j = lane; j < SS; j += 32)
        p[j] = (j <= q) ? expf(p[j] - m) * inv : 0.0f;
}

// ---------------- fused residual-add + LayerNorm ----------------
__global__ void add_ln_kernel(const float* __restrict__ a, const float* __restrict__ r,
                              const float* __restrict__ g, const float* __restrict__ bt,
                              float* __restrict__ o)
{
    int row = blockIdx.x;
    int t = threadIdx.x; // 256 threads, 2 elems each
    long long base = (long long)row * DD;
    float x0 = a[base + t]       + r[base + t];
    float x1 = a[base + t + 256] + r[base + t + 256];
    float sm = x0 + x1, sq = x0 * x0 + x1 * x1;
    #pragma unroll
    for (int off = 16; off; off >>= 1) {
        sm += __shfl_xor_sync(0xffffffffu, sm, off);
        sq += __shfl_xor_sync(0xffffffffu, sq, off);
    }
    __shared__ float sh[2][8];
    if ((t & 31) == 0) { sh[0][t >> 5] = sm; sh[1][t >> 5] = sq; }
    __syncthreads();
    float S = 0, Q = 0;
    #pragma unroll
    for (int j = 0; j < 8; j++) { S += sh[0][j]; Q += sh[1][j]; }
    float mean = S * (1.0f / DD);
    float var  = Q * (1.0f / DD) - mean * mean;
    float inv  = rsqrtf(var + 1e-9f);
    o[base + t]       = (x0 - mean) * inv * g[t]       + bt[t];
    o[base + t + 256] = (x1 - mean) * inv * g[t + 256] + bt[t + 256];
}

// ---------------- final projection: out = h[:, -48:, :] @ out_w + out_b ----------------
__global__ void out_kernel(const float* __restrict__ h, const float* __restrict__ w,
                           const float* __restrict__ b, float* __restrict__ out)
{
    int r = blockIdx.x * 4 + (threadIdx.x >> 5);
    if (r >= BB * NFUT) return;
    int lane = threadIdx.x & 31;
    int bb = r / NFUT, si = r % NFUT;
    const float* hr = h + ((long long)bb * SS + (SS - NFUT) + si) * DD;
    float acc = 0.0f;
    for (int d = lane; d < DD; d += 32) acc += hr[d] * w[d];
    #pragma unroll
    for (int o = 16; o; o >>= 1) acc += __shfl_xor_sync(0xffffffffu, acc, o);
    if (lane == 0) out[r] = acc + b[0];
}

// ---------------- host-side launcher ----------------
static inline void launch_gemm(const float* A, const float* B, const float* bias, float* C,
                               int M, int N, int K, int lda, int ldb, int ldc,
                               long long sAb, long long sAh, long long sBb, long long sBh,
                               long long sCb, long long sCh, int Hs, int Z,
                               float alpha, int flags)
{
    dim3 grid((N + TN - 1) / TN, (M + TM - 1) / TM, Z);
    gemm_tf32<<<grid, 256>>>(A, B, bias, C, M, N, K, lda, ldb, ldc,
                             sAb, sAh, sBb, sBh, sCb, sCh, Hs, alpha, flags);
}

extern "C" void kernel_launch(void* const* d_in, const int* in_sizes, int n_in,
                              void* d_out, int out_size)
{
    const float* x    = (const float*)d_in[0];
    // d_in[1] = mask (unused; causality applied analytically)
    const float* in_w = (const float*)d_in[2];
    const float* in_b = (const float*)d_in[3];
    const float* wq_w = (const float*)d_in[4];
    const float* wq_b = (const float*)d_in[5];
    const float* wk_w = (const float*)d_in[6];
    const float* wk_b = (const float*)d_in[7];
    const float* wv_w = (const float*)d_in[8];
    const float* wv_b = (const float*)d_in[9];
    const float* dn_w = (const float*)d_in[10];
    const float* dn_b = (const float*)d_in[11];
    const float* mh_w = (const float*)d_in[12];
    const float* mh_b = (const float*)d_in[13];
    const float* mo_w = (const float*)d_in[14];
    const float* mo_b = (const float*)d_in[15];
    const float* ln1g = (const float*)d_in[16];
    const float* ln1b = (const float*)d_in[17];
    const float* ln3g = (const float*)d_in[18];
    const float* ln3b = (const float*)d_in[19];
    const float* ow   = (const float*)d_in[20];
    const float* ob   = (const float*)d_in[21];

    float *h, *h1, *t, *q, *k, *v, *sc, *mlp;
    cudaGetSymbolAddress((void**)&h,   g_h);
    cudaGetSymbolAddress((void**)&h1,  g_h1);
    cudaGetSymbolAddress((void**)&t,   g_t);
    cudaGetSymbolAddress((void**)&q,   g_q);
    cudaGetSymbolAddress((void**)&k,   g_k);
    cudaGetSymbolAddress((void**)&v,   g_v);
    cudaGetSymbolAddress((void**)&sc,  g_s);
    cudaGetSymbolAddress((void**)&mlp, g_mlp);

    const float inv_sqrt_d = 0.044194173824159216f; // 1/sqrt(512)

    embed_kernel<<<(MTOK * DD + 255) / 256, 256>>>(x, in_w, in_b, h);

    for (int i = 0; i < LL; i++) {
        const float* wq = wq_w + (long long)i * DD * DH;
        const float* wk = wk_w + (long long)i * DD * DH;
        const float* wv = wv_w + (long long)i * DD * DH;

        // Q,K,V: [10752,512] @ [512,4096] -> [B,S,H,Dh] row-major (==[10752,4096])
        launch_gemm(h, wq, wq_b + (long long)i * DH, q, MTOK, DH, DD, DD, DH, DH,
                    0,0,0,0,0,0, 1, 1, 1.0f, FLAG_BIAS);
        launch_gemm(h, wk, wk_b + (long long)i * DH, k, MTOK, DH, DD, DD, DH, DH,
                    0,0,0,0,0,0, 1, 1, 1.0f, FLAG_BIAS);
        launch_gemm(h, wv, wv_b + (long long)i * DH, v, MTOK, DH, DD, DD, DH, DH,
                    0,0,0,0,0,0, 1, 1, 1.0f, FLAG_BIAS);

        // scores[z=b*H+h][q][j] = (Q . K) * inv_sqrt_d   (NT, strided-batched over 512)
        launch_gemm(q, k, nullptr, sc, SS, SS, DD, DH, DH, SS,
                    (long long)SS * DH, DD,                 // A: b-stride, h-stride
                    (long long)SS * DH, DD,                 // B: same
                    (long long)HH * SS * SS, (long long)SS * SS, // C
                    HH, BB * HH, inv_sqrt_d, FLAG_TRB);

        softmax_kernel<<<(BB * HH * SS + 7) / 8, 256>>>(sc);

        // context = P @ V -> written straight into [b, s, h*512+d] layout (reuse q buffer)
        launch_gemm(sc, v, nullptr, q, SS, DD, SS, SS, DH, DH,
                    (long long)HH * SS * SS, (long long)SS * SS,
                    (long long)SS * DH, DD,
                    (long long)SS * DH, DD,
                    HH, BB * HH, 1.0f, 0);

        // dn: [10752,4096] @ [4096,512]
        launch_gemm(q, dn_w + (long long)i * DH * DD, dn_b + (long long)i * DD, t,
                    MTOK, DD, DH, DH, DD, DD, 0,0,0,0,0,0, 1, 1, 1.0f, FLAG_BIAS);

        add_ln_kernel<<<MTOK, 256>>>(t, h, ln1g + (long long)i * DD, ln1b + (long long)i * DD, h1);

        // MLP up (+relu): [10752,512] @ [512,2048]
        launch_gemm(h1, mh_w + (long long)i * DD * HID, mh_b + (long long)i * HID, mlp,
                    MTOK, HID, DD, DD, HID, HID, 0,0,0,0,0,0, 1, 1, 1.0f, FLAG_BIAS | FLAG_RELU);
        // MLP down: [10752,2048] @ [2048,512]
        launch_gemm(mlp, mo_w + (long long)i * HID * DD, mo_b + (long long)i * DD, t,
                    MTOK, DD, HID, HID, DD, DD, 0,0,0,0,0,0, 1, 1, 1.0f, FLAG_BIAS);

        add_ln_kernel<<<MTOK, 256>>>(t, h1, ln3g + (long long)i * DD, ln3b + (long long)i * DD, h);
    }

    out_kernel<<<(BB * NFUT + 3) / 4, 128>>>(h, ow, ob, (float*)d_out);
}

// round 3
// speedup vs baseline: 1.8174x; 1.8174x over previous
#include <cuda_runtime.h>
#include <mma.h>
#include <math.h>

using namespace nvcuda;

// ---------------- problem constants ----------------
#define BB 64
#define SS 168
#define F_IN 10
#define DD 512
#define HH 8
#define LL 4
#define HID 2048
#define NFUT 48
#define DH (DD*HH)          // 4096
#define MTOK (BB*SS)        // 10752

// ---------------- scratch ----------------
__device__ float g_h  [MTOK*DD];
__device__ float g_h1 [MTOK*DD];
__device__ float g_t  [MTOK*DD];
__device__ float g_q  [MTOK*DH];
__device__ float g_k  [MTOK*DH];
__device__ float g_v  [MTOK*DH];
__device__ float g_s  [BB*HH*SS*SS];
__device__ float g_mlp[MTOK*HID];

// ---------------- GEMM config ----------------
#define TM 128
#define TN 128
#define TK 32
#define LDA_S 36           // padded row stride (floats), 144B = 9*16B (wmma-legal)
#define LDB_S 132          // 528B = 33*16B (wmma-legal)
#define A_TILE_FLTS (TM*LDA_S)            // 4608
#define B_TILE_FLTS 4608                  // max(32*132=4224, 128*36=4608)
#define STAGE_FLTS  (A_TILE_FLTS + B_TILE_FLTS)   // 9216
#define SMEM_BYTES  (2*STAGE_FLTS*4)              // 73728

__device__ __forceinline__ void cp16(void* dst, const void* src, int bytes) {
    unsigned d = (unsigned)__cvta_generic_to_shared(dst);
    asm volatile("cp.async.cg.shared.global [%0], [%1], 16, %2;\n"
                 :: "r"(d), "l"(src), "r"(bytes));
}
__device__ __forceinline__ void cp_commit() {
    asm volatile("cp.async.commit_group;\n" ::: "memory");
}
__device__ __forceinline__ void cp_wait1() {
    asm volatile("cp.async.wait_group 1;\n" ::: "memory");
}
__device__ __forceinline__ void cp_wait0() {
    asm volatile("cp.async.wait_group 0;\n" ::: "memory");
}

// C[M,N] = alpha * A[M,K] @ (TRB ? B^T : B) (+bias) (+relu); strided-batched over z.
template<bool TRB, bool BIAS, bool RELU>
__global__ void __launch_bounds__(256, 2)
gemm_t(const float* __restrict__ A, const float* __restrict__ Bm,
       const float* __restrict__ bias, float* __restrict__ C,
       int M, int N, int K, int lda, int ldb, int ldc,
       long long sAb, long long sAh, long long sBb, long long sBh,
       long long sCb, long long sCh, int Hs, float alpha)
{
    extern __shared__ float smem[];

    const int z = blockIdx.z;
    const int b = z / Hs, hh = z % Hs;
    A  += (long long)b * sAb + (long long)hh * sAh;
    Bm += (long long)b * sBb + (long long)hh * sBh;
    C  += (long long)b * sCb + (long long)hh * sCh;

    const int tile_m = blockIdx.y * TM;
    const int tile_n = blockIdx.x * TN;
    const int tid  = threadIdx.x;
    const int warp = tid >> 5;
    const int lane = tid & 31;
    const int wm = warp & 3;   // 4 warps along M
    const int wn = warp >> 2;  // 2 warps along N

    wmma::fragment<wmma::accumulator, 16, 16, 8, float> cf[2][4];
    #pragma unroll
    for (int i = 0; i < 2; i++)
        #pragma unroll
        for (int j = 0; j < 4; j++)
            wmma::fill_fragment(cf[i][j], 0.0f);

    const int nIter = (K + TK - 1) / TK;

    // ---- stage loader: iter -> buffer ----
    auto stage = [&](int it, int bufi) {
        const int k0 = it * TK;
        float* sA = smem + bufi * STAGE_FLTS;
        float* sB = sA + A_TILE_FLTS;
        // A tile: 128 rows x 32 cols -> 1024 16B chunks
        #pragma unroll
        for (int c = tid; c < 1024; c += 256) {
            int r = c >> 3, kc = (c & 7) * 4;
            int gm = tile_m + r, gk = k0 + kc;
            int bytes = (gm < M && gk + 4 <= K) ? 16 : 0;
            const float* src = bytes ? (A + (long long)gm * lda + gk) : A;
            cp16(sA + r * LDA_S + kc, src, bytes);
        }
        if (!TRB) {
            // B tile: 32 rows(k) x 128 cols(n)
            #pragma unroll
            for (int c = tid; c < 1024; c += 256) {
                int r = c >> 5, nc = (c & 31) * 4;
                int gk = k0 + r, gn = tile_n + nc;
                int bytes = (gk < K && gn + 4 <= N) ? 16 : 0;
                const float* src = bytes ? (Bm + (long long)gk * ldb + gn) : Bm;
                cp16(sB + r * LDB_S + nc, src, bytes);
            }
        } else {
            // B^T tile: 128 rows(n) x 32 cols(k)
            #pragma unroll
            for (int c = tid; c < 1024; c += 256) {
                int r = c >> 3, kc = (c & 7) * 4;
                int gn = tile_n + r, gk = k0 + kc;
                int bytes = (gn < N && gk + 4 <= K) ? 16 : 0;
                const float* src = bytes ? (Bm + (long long)gn * ldb + gk) : Bm;
                cp16(sB + r * LDA_S + kc, src, bytes);
            }
        }
    };

    stage(0, 0);
    cp_commit();

    int buf = 0;
    for (int it = 0; it < nIter; ++it) {
        if (it + 1 < nIter) { stage(it + 1, buf ^ 1); cp_commit(); cp_wait1(); }
        else cp_wait0();
        __syncthreads();

        const float* sA = smem + buf * STAGE_FLTS;
        const float* sB = sA + A_TILE_FLTS;

        #pragma unroll
        for (int kk = 0; kk < TK; kk += 8) {
            wmma::fragment<wmma::matrix_a, 16, 16, 8, wmma::precision::tf32, wmma::row_major> af[2];
            #pragma unroll
            for (int mi = 0; mi < 2; mi++) {
                wmma::load_matrix_sync(af[mi], sA + (wm * 32 + mi * 16) * LDA_S + kk, LDA_S);
                #pragma unroll
                for (int e = 0; e < af[mi].num_elements; e++)
                    af[mi].x[e] = wmma::__float_to_tf32(af[mi].x[e]);
            }
            if (!TRB) {
                wmma::fragment<wmma::matrix_b, 16, 16, 8, wmma::precision::tf32, wmma::row_major> bf[4];
                #pragma unroll
                for (int ni = 0; ni < 4; ni++) {
                    wmma::load_matrix_sync(bf[ni], sB + kk * LDB_S + (wn * 64 + ni * 16), LDB_S);
                    #pragma unroll
                    for (int e = 0; e < bf[ni].num_elements; e++)
                        bf[ni].x[e] = wmma::__float_to_tf32(bf[ni].x[e]);
                }
                #pragma unroll
                for (int mi = 0; mi < 2; mi++)
                    #pragma unroll
                    for (int ni = 0; ni < 4; ni++)
                        wmma::mma_sync(cf[mi][ni], af[mi], bf[ni], cf[mi][ni]);
            } else {
                wmma::fragment<wmma::matrix_b, 16, 16, 8, wmma::precision::tf32, wmma::col_major> bf[4];
                #pragma unroll
                for (int ni = 0; ni < 4; ni++) {
                    wmma::load_matrix_sync(bf[ni], sB + (wn * 64 + ni * 16) * LDA_S + kk, LDA_S);
                    #pragma unroll
                    for (int e = 0; e < bf[ni].num_elements; e++)
                        bf[ni].x[e] = wmma::__float_to_tf32(bf[ni].x[e]);
                }
                #pragma unroll
                for (int mi = 0; mi < 2; mi++)
                    #pragma unroll
                    for (int ni = 0; ni < 4; ni++)
                        wmma::mma_sync(cf[mi][ni], af[mi], bf[ni], cf[mi][ni]);
            }
        }
        __syncthreads();
        buf ^= 1;
    }

    // ---- epilogue: stage fragments through smem; ldm=20 floats (80B, wmma-legal) ----
    float* stg = smem + warp * 320;  // 16x20 per warp
    const bool full = (tile_m + TM <= M) && (tile_n + TN <= N);
    #pragma unroll
    for (int mi = 0; mi < 2; mi++) {
        #pragma unroll
        for (int ni = 0; ni < 4; ni++) {
            wmma::store_matrix_sync(stg, cf[mi][ni], 20, wmma::mem_row_major);
            __syncwarp();
            #pragma unroll
            for (int e = lane; e < 256; e += 32) {
                int rr = e >> 4, cc = e & 15;
                int gm = tile_m + wm * 32 + mi * 16 + rr;
                int gn = tile_n + wn * 64 + ni * 16 + cc;
                if (full || (gm < M && gn < N)) {
                    float v = stg[rr * 20 + cc] * alpha;
                    if (BIAS) v += bias[gn];
                    if (RELU) v = fmaxf(v, 0.0f);
                    C[(long long)gm * ldc + gn] = v;
                }
            }
            __syncwarp();
        }
    }
}

// ---------------- embedding ----------------
__global__ void embed_kernel(const float* __restrict__ x, const float* __restrict__ w,
                             const float* __restrict__ b, float* __restrict__ h)
{
    int idx = blockIdx.x * 256 + threadIdx.x;
    if (idx >= MTOK * DD) return;
    int row = idx / DD, d = idx % DD;
    int s = row % SS;
    const float* xr = x + row * F_IN;
    float acc = b[d];
    #pragma unroll
    for (int f = 0; f < F_IN; f++) acc += xr[f] * w[f * DD + d];
    acc *= 22.627416997969522f;
    float di2 = (float)(2 * (d >> 1));
    float ang = (float)s * expf(di2 * (-9.210340371976184f / (float)DD));
    float pe = (d & 1) ? cosf(ang) : sinf(ang);
    h[idx] = acc + pe;
}

// ---------------- causal softmax ----------------
__global__ void softmax_kernel(float* __restrict__ s)
{
    int row = blockIdx.x * 8 + (threadIdx.x >> 5);
    if (row >= BB * HH * SS) return;
    int lane = threadIdx.x & 31;
    int q = row % SS;
    float* p = s + (long long)row * SS;

    float m = -1e30f;
    for (int j = lane; j <= q; j += 32) m = fmaxf(m, p[j]);
    #pragma unroll
    for (int o = 16; o; o >>= 1) m = fmaxf(m, __shfl_xor_sync(0xffffffffu, m, o));

    float sum = 0.0f;
    for (int j = lane; j <= q; j += 32) sum += expf(p[j] - m);
    #pragma unroll
    for (int o = 16; o; o >>= 1) sum += __shfl_xor_sync(0xffffffffu, sum, o);
    float inv = 1.0f / sum;

    for (int j = lane; j < SS; j += 32)
        p[j] = (j <= q) ? expf(p[j] - m) * inv : 0.0f;
}

// ---------------- fused residual-add + LayerNorm ----------------
__global__ void add_ln_kernel(const float* __restrict__ a, const float* __restrict__ r,
                              const float* __restrict__ g, const float* __restrict__ bt,
                              float* __restrict__ o)
{
    int row = blockIdx.x;
    int t = threadIdx.x;
    long long base = (long long)row * DD;
    float x0 = a[base + t]       + r[base + t];
    float x1 = a[base + t + 256] + r[base + t + 256];
    float sm = x0 + x1, sq = x0 * x0 + x1 * x1;
    #pragma unroll
    for (int off = 16; off; off >>= 1) {
        sm += __shfl_xor_sync(0xffffffffu, sm, off);
        sq += __shfl_xor_sync(0xffffffffu, sq, off);
    }
    __shared__ float sh[2][8];
    if ((t & 31) == 0) { sh[0][t >> 5] = sm; sh[1][t >> 5] = sq; }
    __syncthreads();
    float S = 0, Q = 0;
    #pragma unroll
    for (int j = 0; j < 8; j++) { S += sh[0][j]; Q += sh[1][j]; }
    float mean = S * (1.0f / DD);
    float var  = Q * (1.0f / DD) - mean * mean;
    float inv  = rsqrtf(var + 1e-9f);
    o[base + t]       = (x0 - mean) * inv * g[t]       + bt[t];
    o[base + t + 256] = (x1 - mean) * inv * g[t + 256] + bt[t + 256];
}

// ---------------- final projection ----------------
__global__ void out_kernel(const float* __restrict__ h, const float* __restrict__ w,
                           const float* __restrict__ b, float* __restrict__ out)
{
    int r = blockIdx.x * 4 + (threadIdx.x >> 5);
    if (r >= BB * NFUT) return;
    int lane = threadIdx.x & 31;
    int bb = r / NFUT, si = r % NFUT;
    const float* hr = h + ((long long)bb * SS + (SS - NFUT) + si) * DD;
    float acc = 0.0f;
    for (int d = lane; d < DD; d += 32) acc += hr[d] * w[d];
    #pragma unroll
    for (int o = 16; o; o >>= 1) acc += __shfl_xor_sync(0xffffffffu, acc, o);
    if (lane == 0) out[r] = acc + b[0];
}

// ---------------- host-side launcher ----------------
#define FLAG_RELU 1
#define FLAG_TRB  2
#define FLAG_BIAS 4

static inline void launch_gemm(const float* A, const float* B, const float* bias, float* C,
                               int M, int N, int K, int lda, int ldb, int ldc,
                               long long sAb, long long sAh, long long sBb, long long sBh,
                               long long sCb, long long sCh, int Hs, int Z,
                               float alpha, int flags)
{
    dim3 grid((N + TN - 1) / TN, (M + TM - 1) / TM, Z);
#define LGO(T,Bi,R) do { \
        static bool s_set = false; \
        if (!s_set) { cudaFuncSetAttribute(gemm_t<T,Bi,R>, cudaFuncAttributeMaxDynamicSharedMemorySize, SMEM_BYTES); s_set = true; } \
        gemm_t<T,Bi,R><<<grid, 256, SMEM_BYTES>>>(A, B, bias, C, M, N, K, lda, ldb, ldc, \
            sAb, sAh, sBb, sBh, sCb, sCh, Hs, alpha); } while(0)

    if (flags == FLAG_BIAS)                       LGO(false, true,  false);
    else if (flags == (FLAG_BIAS | FLAG_RELU))    LGO(false, true,  true);
    else if (flags == FLAG_TRB)                   LGO(true,  false, false);
    else                                          LGO(false, false, false);
#undef LGO
}

extern "C" void kernel_launch(void* const* d_in, const int* in_sizes, int n_in,
                              void* d_out, int out_size)
{
    const float* x    = (const float*)d_in[0];
    const float* in_w = (const float*)d_in[2];
    const float* in_b = (const float*)d_in[3];
    const float* wq_w = (const float*)d_in[4];
    const float* wq_b = (const float*)d_in[5];
    const float* wk_w = (const float*)d_in[6];
    const float* wk_b = (const float*)d_in[7];
    const float* wv_w = (const float*)d_in[8];
    const float* wv_b = (const float*)d_in[9];
    const float* dn_w = (const float*)d_in[10];
    const float* dn_b = (const float*)d_in[11];
    const float* mh_w = (const float*)d_in[12];
    const float* mh_b = (const float*)d_in[13];
    const float* mo_w = (const float*)d_in[14];
    const float* mo_b = (const float*)d_in[15];
    const float* ln1g = (const float*)d_in[16];
    const float* ln1b = (const float*)d_in[17];
    const float* ln3g = (const float*)d_in[18];
    const float* ln3b = (const float*)d_in[19];
    const float* ow   = (const float*)d_in[20];
    const float* ob   = (const float*)d_in[21];

    float *h, *h1, *t, *q, *k, *v, *sc, *mlp;
    cudaGetSymbolAddress((void**)&h,   g_h);
    cudaGetSymbolAddress((void**)&h1,  g_h1);
    cudaGetSymbolAddress((void**)&t,   g_t);
    cudaGetSymbolAddress((void**)&q,   g_q);
    cudaGetSymbolAddress((void**)&k,   g_k);
    cudaGetSymbolAddress((void**)&v,   g_v);
    cudaGetSymbolAddress((void**)&sc,  g_s);
    cudaGetSymbolAddress((void**)&mlp, g_mlp);

    const float inv_sqrt_d = 0.044194173824159216f;

    embed_kernel<<<(MTOK * DD + 255) / 256, 256>>>(x, in_w, in_b, h);

    for (int i = 0; i < LL; i++) {
        const float* wq = wq_w + (long long)i * DD * DH;
        const float* wk = wk_w + (long long)i * DD * DH;
        const float* wv = wv_w + (long long)i * DD * DH;

        launch_gemm(h, wq, wq_b + (long long)i * DH, q, MTOK, DH, DD, DD, DH, DH,
                    0,0,0,0,0,0, 1, 1, 1.0f, FLAG_BIAS);
        launch_gemm(h, wk, wk_b + (long long)i * DH, k, MTOK, DH, DD, DD, DH, DH,
                    0,0,0,0,0,0, 1, 1, 1.0f, FLAG_BIAS);
        launch_gemm(h, wv, wv_b + (long long)i * DH, v, MTOK, DH, DD, DD, DH, DH,
                    0,0,0,0,0,0, 1, 1, 1.0f, FLAG_BIAS);

        // scores = Q @ K^T * inv_sqrt_d, batched over (b,h)
        launch_gemm(q, k, nullptr, sc, SS, SS, DD, DH, DH, SS,
                    (long long)SS * DH, DD,
                    (long long)SS * DH, DD,
                    (long long)HH * SS * SS, (long long)SS * SS,
                    HH, BB * HH, inv_sqrt_d, FLAG_TRB);

        softmax_kernel<<<(BB * HH * SS + 7) / 8, 256>>>(sc);

        // context = P @ V
        launch_gemm(sc, v, nullptr, q, SS, DD, SS, SS, DH, DH,
                    (long long)HH * SS * SS, (long long)SS * SS,
                    (long long)SS * DH, DD,
                    (long long)SS * DH, DD,
                    HH, BB * HH, 1.0f, 0);

        launch_gemm(q, dn_w + (long long)i * DH * DD, dn_b + (long long)i * DD, t,
                    MTOK, DD, DH, DH, DD, DD, 0,0,0,0,0,0, 1, 1, 1.0f, FLAG_BIAS);

        add_ln_kernel<<<MTOK, 256>>>(t, h, ln1g + (long long)i * DD, ln1b + (long long)i * DD, h1);

        launch_gemm(h1, mh_w + (long long)i * DD * HID, mh_b + (long long)i * HID, mlp,
                    MTOK, HID, DD, DD, HID, HID, 0,0,0,0,0,0, 1, 1, 1.0f, FLAG_BIAS | FLAG_RELU);
        launch_gemm(mlp, mo_w + (long long)i * HID * DD, mo_b + (long long)i * DD, t,
                    MTOK, DD, HID, HID, DD, DD, 0,0,0,0,0,0, 1, 1, 1.0f, FLAG_BIAS);

        add_ln_kernel<<<MTOK, 256>>>(t, h1, ln3g + (long long)i * DD, ln3b + (long long)i * DD, h);
    }

    out_kernel<<<(BB * NFUT + 3) / 4, 128>>>(h, ow, ob, (float*)d_out);
}

// round 6
// speedup vs baseline: 2.0398x; 1.1224x over previous
#include <cuda_runtime.h>
#include <mma.h>
#include <math.h>

using namespace nvcuda;

// ---------------- problem constants ----------------
#define BB 64
#define SS 168
#define F_IN 10
#define DD 512
#define HH 8
#define LL 4
#define HID 2048
#define NFUT 48
#define DH (DD*HH)          // 4096
#define MTOK (BB*SS)        // 10752

__device__ __forceinline__ float rtf(float x) { return wmma::__float_to_tf32(x); }

// ---------------- scratch ----------------
__device__ float g_h  [MTOK*DD];
__device__ float g_h1 [MTOK*DD];
__device__ float g_t  [MTOK*DD];
__device__ float g_q  [MTOK*DH];
__device__ float g_k  [MTOK*DH];
__device__ float g_v  [MTOK*DH];
__device__ float g_s  [BB*HH*SS*SS];
__device__ float g_mlp[MTOK*HID];
// RN-rounded weight copies (tf32-exact fp32)
__device__ float g_wq [LL*DD*DH];
__device__ float g_wk [LL*DD*DH];
__device__ float g_wv [LL*DD*DH];
__device__ float g_wd [LL*DH*DD];
__device__ float g_wmh[LL*DD*HID];
__device__ float g_wmo[LL*HID*DD];

// ---------------- GEMM config ----------------
#define TM 128
#define TN 128
#define TK 32
#define LDA_S 36           // 144B row stride (multiple of 16B)
#define LDB_S 132          // 528B row stride (multiple of 16B)
#define A_TILE_FLTS (TM*LDA_S)            // 4608
#define B_TILE_FLTS 4608
#define STAGE_FLTS  (A_TILE_FLTS + B_TILE_FLTS)   // 9216
#define SMEM_BYTES  (2*STAGE_FLTS*4)              // 73728

__device__ __forceinline__ void cp16(void* dst, const void* src, int bytes) {
    unsigned d = (unsigned)__cvta_generic_to_shared(dst);
    asm volatile("cp.async.cg.shared.global [%0], [%1], 16, %2;\n"
                 :: "r"(d), "l"(src), "r"(bytes));
}
__device__ __forceinline__ void cp16f(void* dst, const void* src) {
    unsigned d = (unsigned)__cvta_generic_to_shared(dst);
    asm volatile("cp.async.cg.shared.global [%0], [%1], 16;\n"
                 :: "r"(d), "l"(src));
}
__device__ __forceinline__ void cp_commit() {
    asm volatile("cp.async.commit_group;\n" ::: "memory");
}
__device__ __forceinline__ void cp_wait1() {
    asm volatile("cp.async.wait_group 1;\n" ::: "memory");
}
__device__ __forceinline__ void cp_wait0() {
    asm volatile("cp.async.wait_group 0;\n" ::: "memory");
}

// ---------------- weight copy + RN tf32 rounding ----------------
__global__ void round_copy_kernel(const float4* __restrict__ src, float4* __restrict__ dst, int n4)
{
    int i = blockIdx.x * 256 + threadIdx.x;
    if (i >= n4) return;
    float4 v = src[i];
    v.x = rtf(v.x); v.y = rtf(v.y); v.z = rtf(v.z); v.w = rtf(v.w);
    dst[i] = v;
}

// C[M,N] = alpha * A[M,K] @ (TRB ? B^T : B) (+bias) (+relu) (RND: RN-round output)
template<bool TRB, bool BIAS, bool RELU, bool RND>
__global__ void __launch_bounds__(256, 2)
gemm_t(const float* __restrict__ A, const float* __restrict__ Bm,
       const float* __restrict__ bias, float* __restrict__ C,
       int M, int N, int K, int lda, int ldb, int ldc,
       long long sAb, long long sAh, long long sBb, long long sBh,
       long long sCb, long long sCh, int Hs, float alpha)
{
    extern __shared__ float smem[];

    const int z = blockIdx.z;
    const int b = z / Hs, hh = z % Hs;
    A  += (long long)b * sAb + (long long)hh * sAh;
    Bm += (long long)b * sBb + (long long)hh * sBh;
    C  += (long long)b * sCb + (long long)hh * sCh;

    const int tile_m = blockIdx.y * TM;
    const int tile_n = blockIdx.x * TN;
    const int tid  = threadIdx.x;
    const int warp = tid >> 5;
    const int lane = tid & 31;
    const int wm = warp & 3;   // 4 warps along M
    const int wn = warp >> 2;  // 2 warps along N

    wmma::fragment<wmma::accumulator, 16, 16, 8, float> cf[2][4];
    #pragma unroll
    for (int i = 0; i < 2; i++)
        #pragma unroll
        for (int j = 0; j < 4; j++)
            wmma::fill_fragment(cf[i][j], 0.0f);

    const int nIter = (K + TK - 1) / TK;
    const bool full = (tile_m + TM <= M) && (tile_n + TN <= N);
    const bool fast = full && ((K & (TK - 1)) == 0);

    // ---- compute on staged buffer (inputs pre-rounded; HMMA truncation is exact) ----
    auto compute = [&](int bufi) {
        const float* sA = smem + bufi * STAGE_FLTS;
        const float* sB = sA + A_TILE_FLTS;
        #pragma unroll
        for (int kk = 0; kk < TK; kk += 8) {
            wmma::fragment<wmma::matrix_a, 16, 16, 8, wmma::precision::tf32, wmma::row_major> af[2];
            #pragma unroll
            for (int mi = 0; mi < 2; mi++)
                wmma::load_matrix_sync(af[mi], sA + (wm * 32 + mi * 16) * LDA_S + kk, LDA_S);
            if (!TRB) {
                wmma::fragment<wmma::matrix_b, 16, 16, 8, wmma::precision::tf32, wmma::row_major> bf[4];
                #pragma unroll
                for (int ni = 0; ni < 4; ni++)
                    wmma::load_matrix_sync(bf[ni], sB + kk * LDB_S + (wn * 64 + ni * 16), LDB_S);
                #pragma unroll
                for (int mi = 0; mi < 2; mi++)
                    #pragma unroll
                    for (int ni = 0; ni < 4; ni++)
                        wmma::mma_sync(cf[mi][ni], af[mi], bf[ni], cf[mi][ni]);
            } else {
                wmma::fragment<wmma::matrix_b, 16, 16, 8, wmma::precision::tf32, wmma::col_major> bf[4];
                #pragma unroll
                for (int ni = 0; ni < 4; ni++)
                    wmma::load_matrix_sync(bf[ni], sB + (wn * 64 + ni * 16) * LDA_S + kk, LDA_S);
                #pragma unroll
                for (int mi = 0; mi < 2; mi++)
                    #pragma unroll
                    for (int ni = 0; ni < 4; ni++)
                        wmma::mma_sync(cf[mi][ni], af[mi], bf[ni], cf[mi][ni]);
            }
        }
    };

    if (fast) {
        // ---- fast path: no tails anywhere; pointer-chasing cp.async ----
        const float* pA[4];
        int dA[4];
        #pragma unroll
        for (int j = 0; j < 4; j++) {
            int c = tid + j * 256;
            int r = c >> 3, kc = (c & 7) * 4;
            dA[j] = r * LDA_S + kc;
            pA[j] = A + (long long)(tile_m + r) * lda + kc;
        }
        const float* pB[4];
        int dB[4];
        long long stepB;
        if (!TRB) {
            #pragma unroll
            for (int j = 0; j < 4; j++) {
                int c = tid + j * 256;
                int r = c >> 5, nc = (c & 31) * 4;
                dB[j] = r * LDB_S + nc;
                pB[j] = Bm + (long long)r * ldb + tile_n + nc;
            }
            stepB = (long long)TK * ldb;
        } else {
            #pragma unroll
            for (int j = 0; j < 4; j++) {
                int c = tid + j * 256;
                int r = c >> 3, kc = (c & 7) * 4;
                dB[j] = r * LDA_S + kc;
                pB[j] = Bm + (long long)(tile_n + r) * ldb + kc;
            }
            stepB = TK;
        }

        auto stageF = [&](int bufi) {
            float* sA = smem + bufi * STAGE_FLTS;
            float* sB = sA + A_TILE_FLTS;
            #pragma unroll
            for (int j = 0; j < 4; j++) { cp16f(sA + dA[j], pA[j]); pA[j] += TK; }
            #pragma unroll
            for (int j = 0; j < 4; j++) { cp16f(sB + dB[j], pB[j]); pB[j] += stepB; }
        };

        stageF(0);
        cp_commit();
        int buf = 0;
        for (int it = 0; it < nIter; ++it) {
            if (it + 1 < nIter) { stageF(buf ^ 1); cp_commit(); cp_wait1(); }
            else cp_wait0();
            __syncthreads();
            compute(buf);
            __syncthreads();
            buf ^= 1;
        }
    } else {
        // ---- slow path: fully predicated (tails zero-filled via src-size=0) ----
        auto stageS = [&](int it, int bufi) {
            const int k0 = it * TK;
            float* sA = smem + bufi * STAGE_FLTS;
            float* sB = sA + A_TILE_FLTS;
            #pragma unroll
            for (int c = tid; c < 1024; c += 256) {
                int r = c >> 3, kc = (c & 7) * 4;
                int gm = tile_m + r, gk = k0 + kc;
                int bytes = (gm < M && gk + 4 <= K) ? 16 : 0;
                const float* src = bytes ? (A + (long long)gm * lda + gk) : A;
                cp16(sA + r * LDA_S + kc, src, bytes);
            }
            if (!TRB) {
                #pragma unroll
                for (int c = tid; c < 1024; c += 256) {
                    int r = c >> 5, nc = (c & 31) * 4;
                    int gk = k0 + r, gn = tile_n + nc;
                    int bytes = (gk < K && gn + 4 <= N) ? 16 : 0;
                    const float* src = bytes ? (Bm + (long long)gk * ldb + gn) : Bm;
                    cp16(sB + r * LDB_S + nc, src, bytes);
                }
            } else {
                #pragma unroll
                for (int c = tid; c < 1024; c += 256) {
                    int r = c >> 3, kc = (c & 7) * 4;
                    int gn = tile_n + r, gk = k0 + kc;
                    int bytes = (gn < N && gk + 4 <= K) ? 16 : 0;
                    const float* src = bytes ? (Bm + (long long)gn * ldb + gk) : Bm;
                    cp16(sB + r * LDA_S + kc, src, bytes);
                }
            }
        };

        stageS(0, 0);
        cp_commit();
        int buf = 0;
        for (int it = 0; it < nIter; ++it) {
            if (it + 1 < nIter) { stageS(it + 1, buf ^ 1); cp_commit(); cp_wait1(); }
            else cp_wait0();
            __syncthreads();
            compute(buf);
            __syncthreads();
            buf ^= 1;
        }
    }

    // ---- epilogue: stage fragments through smem; ldm=20 floats (80B, wmma-legal) ----
    float* stg = smem + warp * 320;  // 16x20 per warp
    #pragma unroll
    for (int mi = 0; mi < 2; mi++) {
        #pragma unroll
        for (int ni = 0; ni < 4; ni++) {
            wmma::store_matrix_sync(stg, cf[mi][ni], 20, wmma::mem_row_major);
            __syncwarp();
            #pragma unroll
            for (int e = lane; e < 256; e += 32) {
                int rr = e >> 4, cc = e & 15;
                int gm = tile_m + wm * 32 + mi * 16 + rr;
                int gn = tile_n + wn * 64 + ni * 16 + cc;
                if (full || (gm < M && gn < N)) {
                    float v = stg[rr * 20 + cc] * alpha;
                    if (BIAS) v += bias[gn];
                    if (RELU) v = fmaxf(v, 0.0f);
                    if (RND)  v = rtf(v);
                    C[(long long)gm * ldc + gn] = v;
                }
            }
            __syncwarp();
        }
    }
}

// ---------------- embedding (output rounded: feeds QKV MMA) ----------------
__global__ void embed_kernel(const float* __restrict__ x, const float* __restrict__ w,
                             const float* __restrict__ b, float* __restrict__ h)
{
    int idx = blockIdx.x * 256 + threadIdx.x;
    if (idx >= MTOK * DD) return;
    int row = idx / DD, d = idx % DD;
    int s = row % SS;
    const float* xr = x + row * F_IN;
    float acc = b[d];
    #pragma unroll
    for (int f = 0; f < F_IN; f++) acc += xr[f] * w[f * DD + d];
    acc *= 22.627416997969522f;
    float di2 = (float)(2 * (d >> 1));
    float ang = (float)s * expf(di2 * (-9.210340371976184f / (float)DD));
    float pe = (d & 1) ? cosf(ang) : sinf(ang);
    h[idx] = rtf(acc + pe);
}

// ---------------- causal softmax (probs rounded: feed PV MMA) ----------------
__global__ void softmax_kernel(float* __restrict__ s)
{
    int row = blockIdx.x * 8 + (threadIdx.x >> 5);
    if (row >= BB * HH * SS) return;
    int lane = threadIdx.x & 31;
    int q = row % SS;
    float* p = s + (long long)row * SS;

    float m = -1e30f;
    for (int j = lane; j <= q; j += 32) m = fmaxf(m, p[j]);
    #pragma unroll
    for (int o = 16; o; o >>= 1) m = fmaxf(m, __shfl_xor_sync(0xffffffffu, m, o));

    float sum = 0.0f;
    for (int j = lane; j <= q; j += 32) sum += expf(p[j] - m);
    #pragma unroll
    for (int o = 16; o; o >>= 1) sum += __shfl_xor_sync(0xffffffffu, sum, o);
    float inv = 1.0f / sum;

    for (int j = lane; j < SS; j += 32)
        p[j] = (j <= q) ? rtf(expf(p[j] - m) * inv) : 0.0f;
}

// ---------------- fused residual-add + LayerNorm (output rounded: feeds MMA) ----------------
__global__ void add_ln_kernel(const float* __restrict__ a, const float* __restrict__ r,
                              const float* __restrict__ g, const float* __restrict__ bt,
                              float* __restrict__ o)
{
    int row = blockIdx.x;
    int t = threadIdx.x;
    long long base = (long long)row * DD;
    float x0 = a[base + t]       + r[base + t];
    float x1 = a[base + t + 256] + r[base + t + 256];
    float sm = x0 + x1, sq = x0 * x0 + x1 * x1;
    #pragma unroll
    for (int off = 16; off; off >>= 1) {
        sm += __shfl_xor_sync(0xffffffffu, sm, off);
        sq += __shfl_xor_sync(0xffffffffu, sq, off);
    }
    __shared__ float sh[2][8];
    if ((t & 31) == 0) { sh[0][t >> 5] = sm; sh[1][t >> 5] = sq; }
    __syncthreads();
    float S = 0, Q = 0;
    #pragma unroll
    for (int j = 0; j < 8; j++) { S += sh[0][j]; Q += sh[1][j]; }
    float mean = S * (1.0f / DD);
    float var  = Q * (1.0f / DD) - mean * mean;
    float inv  = rsqrtf(var + 1e-9f);
    o[base + t]       = rtf((x0 - mean) * inv * g[t]       + bt[t]);
    o[base + t + 256] = rtf((x1 - mean) * inv * g[t + 256] + bt[t + 256]);
}

// ---------------- final projection (fp32 dot; h rounding already applied) ----------------
__global__ void out_kernel(const float* __restrict__ h, const float* __restrict__ w,
                           const float* __restrict__ b, float* __restrict__ out)
{
    int r = blockIdx.x * 4 + (threadIdx.x >> 5);
    if (r >= BB * NFUT) return;
    int lane = threadIdx.x & 31;
    int bb = r / NFUT, si = r % NFUT;
    const float* hr = h + ((long long)bb * SS + (SS - NFUT) + si) * DD;
    float acc = 0.0f;
    for (int d = lane; d < DD; d += 32) acc += hr[d] * w[d];
    #pragma unroll
    for (int o = 16; o; o >>= 1) acc += __shfl_xor_sync(0xffffffffu, acc, o);
    if (lane == 0) out[r] = acc + b[0];
}

// ---------------- host-side launcher ----------------
#define FLAG_RELU 1
#define FLAG_TRB  2
#define FLAG_BIAS 4
#define FLAG_RND  8

static inline void launch_gemm(const float* A, const float* B, const float* bias, float* C,
                               int M, int N, int K, int lda, int ldb, int ldc,
                               long long sAb, long long sAh, long long sBb, long long sBh,
                               long long sCb, long long sCh, int Hs, int Z,
                               float alpha, int flags)
{
    dim3 grid((N + TN - 1) / TN, (M + TM - 1) / TM, Z);
#define LGO(T,Bi,R,Rn) do { \
        static bool s_set = false; \
        if (!s_set) { cudaFuncSetAttribute(gemm_t<T,Bi,R,Rn>, cudaFuncAttributeMaxDynamicSharedMemorySize, SMEM_BYTES); s_set = true; } \
        gemm_t<T,Bi,R,Rn><<<grid, 256, SMEM_BYTES>>>(A, B, bias, C, M, N, K, lda, ldb, ldc, \
            sAb, sAh, sBb, sBh, sCb, sCh, Hs, alpha); } while(0)

    if (flags == (FLAG_BIAS | FLAG_RND))                       LGO(false, true,  false, true);
    else if (flags == FLAG_BIAS)                               LGO(false, true,  false, false);
    else if (flags == (FLAG_BIAS | FLAG_RELU | FLAG_RND))      LGO(false, true,  true,  true);
    else if (flags == FLAG_TRB)                                LGO(true,  false, false, false);
    else if (flags == FLAG_RND)                                LGO(false, false, false, true);
    else                                                       LGO(false, false, false, false);
#undef LGO
}

extern "C" void kernel_launch(void* const* d_in, const int* in_sizes, int n_in,
                              void* d_out, int out_size)
{
    const float* x    = (const float*)d_in[0];
    const float* in_w = (const float*)d_in[2];
    const float* in_b = (const float*)d_in[3];
    const float* wq_w = (const float*)d_in[4];
    const float* wq_b = (const float*)d_in[5];
    const float* wk_w = (const float*)d_in[6];
    const float* wk_b = (const float*)d_in[7];
    const float* wv_w = (const float*)d_in[8];
    const float* wv_b = (const float*)d_in[9];
    const float* dn_w = (const float*)d_in[10];
    const float* dn_b = (const float*)d_in[11];
    const float* mh_w = (const float*)d_in[12];
    const float* mh_b = (const float*)d_in[13];
    const float* mo_w = (const float*)d_in[14];
    const float* mo_b = (const float*)d_in[15];
    const float* ln1g = (const float*)d_in[16];
    const float* ln1b = (const float*)d_in[17];
    const float* ln3g = (const float*)d_in[18];
    const float* ln3b = (const float*)d_in[19];
    const float* ow   = (const float*)d_in[20];
    const float* ob   = (const float*)d_in[21];

    float *h, *h1, *t, *q, *k, *v, *sc, *mlp;
    float *wq, *wk, *wv, *wd, *wmh, *wmo;
    cudaGetSymbolAddress((void**)&h,   g_h);
    cudaGetSymbolAddress((void**)&h1,  g_h1);
    cudaGetSymbolAddress((void**)&t,   g_t);
    cudaGetSymbolAddress((void**)&q,   g_q);
    cudaGetSymbolAddress((void**)&k,   g_k);
    cudaGetSymbolAddress((void**)&v,   g_v);
    cudaGetSymbolAddress((void**)&sc,  g_s);
    cudaGetSymbolAddress((void**)&mlp, g_mlp);
    cudaGetSymbolAddress((void**)&wq,  g_wq);
    cudaGetSymbolAddress((void**)&wk,  g_wk);
    cudaGetSymbolAddress((void**)&wv,  g_wv);
    cudaGetSymbolAddress((void**)&wd,  g_wd);
    cudaGetSymbolAddress((void**)&wmh, g_wmh);
    cudaGetSymbolAddress((void**)&wmo, g_wmo);

    // RN-round weights once per call (graph-capturable, deterministic)
    {
        const int n_qkv = LL * DD * DH / 4;   // 2,097,152 float4
        const int n_mlp = LL * DD * HID / 4;  // 1,048,576
        round_copy_kernel<<<(n_qkv + 255) / 256, 256>>>((const float4*)wq_w, (float4*)wq,  n_qkv);
        round_copy_kernel<<<(n_qkv + 255) / 256, 256>>>((const float4*)wk_w, (float4*)wk,  n_qkv);
        round_copy_kernel<<<(n_qkv + 255) / 256, 256>>>((const float4*)wv_w, (float4*)wv,  n_qkv);
        round_copy_kernel<<<(n_qkv + 255) / 256, 256>>>((const float4*)dn_w, (float4*)wd,  n_qkv);
        round_copy_kernel<<<(n_mlp + 255) / 256, 256>>>((const float4*)mh_w, (float4*)wmh, n_mlp);
        round_copy_kernel<<<(n_mlp + 255) / 256, 256>>>((const float4*)mo_w, (float4*)wmo, n_mlp);
    }

    const float inv_sqrt_d = 0.044194173824159216f;

    embed_kernel<<<(MTOK * DD + 255) / 256, 256>>>(x, in_w, in_b, h);

    for (int i = 0; i < LL; i++) {
        launch_gemm(h, wq + (long long)i * DD * DH, wq_b + (long long)i * DH, q, MTOK, DH, DD, DD, DH, DH,
                    0,0,0,0,0,0, 1, 1, 1.0f, FLAG_BIAS | FLAG_RND);
        launch_gemm(h, wk + (long long)i * DD * DH, wk_b + (long long)i * DH, k, MTOK, DH, DD, DD, DH, DH,
                    0,0,0,0,0,0, 1, 1, 1.0f, FLAG_BIAS | FLAG_RND);
        launch_gemm(h, wv + (long long)i * DD * DH, wv_b + (long long)i * DH, v, MTOK, DH, DD, DD, DH, DH,
                    0,0,0,0,0,0, 1, 1, 1.0f, FLAG_BIAS | FLAG_RND);

        // scores = Q @ K^T * inv_sqrt_d, batched over (b,h); consumed by softmax (fp32 ok)
        launch_gemm(q, k, nullptr, sc, SS, SS, DD, DH, DH, SS,
                    (long long)SS * DH, DD,
                    (long long)SS * DH, DD,
                    (long long)HH * SS * SS, (long long)SS * SS,
                    HH, BB * HH, inv_sqrt_d, FLAG_TRB);

        softmax_kernel<<<(BB * HH * SS + 7) / 8, 256>>>(sc);

        // context = P @ V; feeds dn MMA -> round
        launch_gemm(sc, v, nullptr, q, SS, DD, SS, SS, DH, DH,
                    (long long)HH * SS * SS, (long long)SS * SS,
                    (long long)SS * DH, DD,
                    (long long)SS * DH, DD,
                    HH, BB * HH, 1.0f, FLAG_RND);

        launch_gemm(q, wd + (long long)i * DH * DD, dn_b + (long long)i * DD, t,
                    MTOK, DD, DH, DH, DD, DD, 0,0,0,0,0,0, 1, 1, 1.0f, FLAG_BIAS);

        add_ln_kernel<<<MTOK, 256>>>(t, h, ln1g + (long long)i * DD, ln1b + (long long)i * DD, h1);

        launch_gemm(h1, wmh + (long long)i * DD * HID, mh_b + (long long)i * HID, mlp,
                    MTOK, HID, DD, DD, HID, HID, 0,0,0,0,0,0, 1, 1, 1.0f,
                    FLAG_BIAS | FLAG_RELU | FLAG_RND);
        launch_gemm(mlp, wmo + (long long)i * HID * DD, mo_b + (long long)i * DD, t,
                    MTOK, DD, HID, HID, DD, DD, 0,0,0,0,0,0, 1, 1, 1.0f, FLAG_BIAS);

        add_ln_kernel<<<MTOK, 256>>>(t, h1, ln3g + (long long)i * DD, ln3b + (long long)i * DD, h);
    }

    out_kernel<<<(BB * NFUT + 3) / 4, 128>>>(h, ow, ob, (float*)d_out);
}

// round 8
// speedup vs baseline: 7.3836x; 3.6197x over previous
#include <cuda_runtime.h>
#include <cuda_fp16.h>
#include <mma.h>
#include <math.h>

using namespace nvcuda;

// ---------------- problem constants ----------------
#define BB 64
#define SS 168
#define F_IN 10
#define DD 512
#define HH 8
#define LL 4
#define HID 2048
#define NFUT 48
#define DH (DD*HH)          // 4096
#define MTOK (BB*SS)        // 10752

// ---------------- scratch ----------------
__device__ __half g_h  [MTOK*DD];
__device__ __half g_h1 [MTOK*DD];
__device__ float  g_t  [MTOK*DD];       // dn / mo output (fp32, feeds LN)
__device__ __half g_q  [MTOK*DH];       // Q, reused as attention context
__device__ __half g_k  [MTOK*DH];
__device__ __half g_v  [MTOK*DH];
__device__ float  g_s  [BB*HH*SS*SS];   // scores (fp32, softmax input)
__device__ __half g_p  [BB*HH*SS*SS];   // probs (half, PV input)
__device__ __half g_mlp[MTOK*HID];
// half weight copies (original [K,N] layout)
__device__ __half g_wq [LL*DD*DH];
__device__ __half g_wk [LL*DD*DH];
__device__ __half g_wv [LL*DD*DH];
__device__ __half g_wd [LL*DH*DD];
__device__ __half g_wmh[LL*DD*HID];
__device__ __half g_wmo[LL*HID*DD];

// ---------------- GEMM config (fp16, TK=64) ----------------
#define TM 128
#define TN 128
#define TK 64
#define LDA_H 72            // halves; 144B row stride (mult of 16B)
#define LDB_H 136           // halves; 272B row stride (mult of 16B)
#define A_TILE_H (TM*LDA_H)               // 9216 halves
#define B_TILE_H 9216                     // max(64*136=8704, 128*72=9216)
#define STAGE_BYTES ((A_TILE_H + B_TILE_H)*2)   // 36864
#define SMEM_BYTES  (2*STAGE_BYTES)             // 73728

__device__ __forceinline__ void cp16(void* dst, const void* src, int bytes) {
    unsigned d = (unsigned)__cvta_generic_to_shared(dst);
    asm volatile("cp.async.cg.shared.global [%0], [%1], 16, %2;\n"
                 :: "r"(d), "l"(src), "r"(bytes));
}
__device__ __forceinline__ void cp16f(void* dst, const void* src) {
    unsigned d = (unsigned)__cvta_generic_to_shared(dst);
    asm volatile("cp.async.cg.shared.global [%0], [%1], 16;\n"
                 :: "r"(d), "l"(src));
}
__device__ __forceinline__ void cp_commit() {
    asm volatile("cp.async.commit_group;\n" ::: "memory");
}
__device__ __forceinline__ void cp_wait1() {
    asm volatile("cp.async.wait_group 1;\n" ::: "memory");
}
__device__ __forceinline__ void cp_wait0() {
    asm volatile("cp.async.wait_group 0;\n" ::: "memory");
}

// C = alpha * A[M,K] @ (TRB ? B^T : B) (+bias) (+relu); out half (OUTH) or fp32.
template<bool TRB, bool BIAS, bool RELU, bool OUTH>
__global__ void __launch_bounds__(256, 2)
gemm_h(const __half* __restrict__ A, const __half* __restrict__ Bm,
       const float* __restrict__ bias, float* __restrict__ Cf, __half* __restrict__ Ch,
       int M, int N, int K, int lda, int ldb, int ldc,
       long long sAb, long long sAh, long long sBb, long long sBh,
       long long sCb, long long sCh, int Hs, float alpha)
{
    extern __shared__ char smraw[];

    const int z = blockIdx.z;
    const int b = z / Hs, hh = z % Hs;
    A  += (long long)b * sAb + (long long)hh * sAh;
    Bm += (long long)b * sBb + (long long)hh * sBh;
    if (OUTH) Ch += (long long)b * sCb + (long long)hh * sCh;
    else      Cf += (long long)b * sCb + (long long)hh * sCh;

    const int tile_m = blockIdx.y * TM;
    const int tile_n = blockIdx.x * TN;
    const int tid  = threadIdx.x;
    const int warp = tid >> 5;
    const int lane = tid & 31;
    const int wm = warp & 3;   // 4 warps along M (32 rows each)
    const int wn = warp >> 2;  // 2 warps along N (64 cols each)

    wmma::fragment<wmma::accumulator, 16, 16, 16, float> cf[2][4];
    #pragma unroll
    for (int i = 0; i < 2; i++)
        #pragma unroll
        for (int j = 0; j < 4; j++)
            wmma::fill_fragment(cf[i][j], 0.0f);

    const int nIter = (K + TK - 1) / TK;
    const bool full = (tile_m + TM <= M) && (tile_n + TN <= N);
    const bool fast = full && ((K & (TK - 1)) == 0);

    auto compute = [&](int bufi) {
        const __half* sA = (const __half*)(smraw + bufi * STAGE_BYTES);
        const __half* sB = sA + A_TILE_H;
        #pragma unroll
        for (int kk = 0; kk < TK; kk += 16) {
            wmma::fragment<wmma::matrix_a, 16, 16, 16, __half, wmma::row_major> af[2];
            #pragma unroll
            for (int mi = 0; mi < 2; mi++)
                wmma::load_matrix_sync(af[mi], sA + (wm * 32 + mi * 16) * LDA_H + kk, LDA_H);
            if (!TRB) {
                wmma::fragment<wmma::matrix_b, 16, 16, 16, __half, wmma::row_major> bf[4];
                #pragma unroll
                for (int ni = 0; ni < 4; ni++)
                    wmma::load_matrix_sync(bf[ni], sB + kk * LDB_H + (wn * 64 + ni * 16), LDB_H);
                #pragma unroll
                for (int mi = 0; mi < 2; mi++)
                    #pragma unroll
                    for (int ni = 0; ni < 4; ni++)
                        wmma::mma_sync(cf[mi][ni], af[mi], bf[ni], cf[mi][ni]);
            } else {
                wmma::fragment<wmma::matrix_b, 16, 16, 16, __half, wmma::col_major> bf[4];
                #pragma unroll
                for (int ni = 0; ni < 4; ni++)
                    wmma::load_matrix_sync(bf[ni], sB + (wn * 64 + ni * 16) * LDA_H + kk, LDA_H);
                #pragma unroll
                for (int mi = 0; mi < 2; mi++)
                    #pragma unroll
                    for (int ni = 0; ni < 4; ni++)
                        wmma::mma_sync(cf[mi][ni], af[mi], bf[ni], cf[mi][ni]);
            }
        }
    };

    if (fast) {
        // pointer-chasing cp.async; 16B = 8 halves per chunk
        __half* dA[4]; const __half* pA[4];
        __half* dB[4]; const __half* pB[4];
        long long stepB;
        #pragma unroll
        for (int j = 0; j < 4; j++) {
            int c = tid + j * 256;                  // A: 128 rows x 8 chunks
            int r = c >> 3, kc = (c & 7) * 8;
            dA[j] = (__half*)smraw + r * LDA_H + kc;
            pA[j] = A + (long long)(tile_m + r) * lda + kc;
        }
        if (!TRB) {
            #pragma unroll
            for (int j = 0; j < 4; j++) {
                int c = tid + j * 256;              // B: 64 rows x 16 chunks
                int r = c >> 4, nc = (c & 15) * 8;
                dB[j] = (__half*)smraw + A_TILE_H + r * LDB_H + nc;
                pB[j] = Bm + (long long)r * ldb + tile_n + nc;
            }
            stepB = (long long)TK * ldb;
        } else {
            #pragma unroll
            for (int j = 0; j < 4; j++) {
                int c = tid + j * 256;              // B^T: 128 rows x 8 chunks
                int r = c >> 3, kc = (c & 7) * 8;
                dB[j] = (__half*)smraw + A_TILE_H + r * LDA_H + kc;
                pB[j] = Bm + (long long)(tile_n + r) * ldb + kc;
            }
            stepB = TK;
        }

        auto stageF = [&](int bufi) {
            char* base = smraw + bufi * STAGE_BYTES;
            #pragma unroll
            for (int j = 0; j < 4; j++) {
                cp16f(base + ((char*)dA[j] - smraw), pA[j]); pA[j] += TK;
            }
            #pragma unroll
            for (int j = 0; j < 4; j++) {
                cp16f(base + ((char*)dB[j] - smraw), pB[j]); pB[j] += stepB;
            }
        };

        stageF(0);
        cp_commit();
        int buf = 0;
        for (int it = 0; it < nIter; ++it) {
            if (it + 1 < nIter) { stageF(buf ^ 1); cp_commit(); cp_wait1(); }
            else cp_wait0();
            __syncthreads();
            compute(buf);
            __syncthreads();
            buf ^= 1;
        }
    } else {
        auto stageS = [&](int it, int bufi) {
            const int k0 = it * TK;
            __half* sA = (__half*)(smraw + bufi * STAGE_BYTES);
            __half* sB = sA + A_TILE_H;
            #pragma unroll
            for (int c = tid; c < 1024; c += 256) {
                int r = c >> 3, kc = (c & 7) * 8;
                int gm = tile_m + r, gk = k0 + kc;
                int bytes = (gm < M && gk + 8 <= K) ? 16 : 0;
                const __half* src = bytes ? (A + (long long)gm * lda + gk) : A;
                cp16(sA + r * LDA_H + kc, src, bytes);
            }
            if (!TRB) {
                #pragma unroll
                for (int c = tid; c < 1024; c += 256) {
                    int r = c >> 4, nc = (c & 15) * 8;
                    int gk = k0 + r, gn = tile_n + nc;
                    int bytes = (gk < K && gn + 8 <= N) ? 16 : 0;
                    const __half* src = bytes ? (Bm + (long long)gk * ldb + gn) : Bm;
                    cp16(sB + r * LDB_H + nc, src, bytes);
                }
            } else {
                #pragma unroll
                for (int c = tid; c < 1024; c += 256) {
                    int r = c >> 3, kc = (c & 7) * 8;
                    int gn = tile_n + r, gk = k0 + kc;
                    int bytes = (gn < N && gk + 8 <= K) ? 16 : 0;
                    const __half* src = bytes ? (Bm + (long long)gn * ldb + gk) : Bm;
                    cp16(sB + r * LDA_H + kc, src, bytes);
                }
            }
        };

        stageS(0, 0);
        cp_commit();
        int buf = 0;
        for (int it = 0; it < nIter; ++it) {
            if (it + 1 < nIter) { stageS(it + 1, buf ^ 1); cp_commit(); cp_wait1(); }
            else cp_wait0();
            __syncthreads();
            compute(buf);
            __syncthreads();
            buf ^= 1;
        }
    }

    // ---- epilogue: stage fragments through smem (ldm=20 floats = 80B, legal) ----
    float* stg = (float*)smraw + warp * 320;
    #pragma unroll
    for (int mi = 0; mi < 2; mi++) {
        #pragma unroll
        for (int ni = 0; ni < 4; ni++) {
            wmma::store_matrix_sync(stg, cf[mi][ni], 20, wmma::mem_row_major);
            __syncwarp();
            #pragma unroll
            for (int e = lane; e < 256; e += 32) {
                int rr = e >> 4, cc = e & 15;
                int gm = tile_m + wm * 32 + mi * 16 + rr;
                int gn = tile_n + wn * 64 + ni * 16 + cc;
                if (full || (gm < M && gn < N)) {
                    float v = stg[rr * 20 + cc] * alpha;
                    if (BIAS) v += bias[gn];
                    if (RELU) v = fmaxf(v, 0.0f);
                    if (OUTH) Ch[(long long)gm * ldc + gn] = __float2half_rn(v);
                    else      Cf[(long long)gm * ldc + gn] = v;
                }
            }
            __syncwarp();
        }
    }
}

// ---------------- weight fp32 -> fp16 convert ----------------
__global__ void f2h_kernel(const float4* __restrict__ in, __half2* __restrict__ out, int n4)
{
    int i = blockIdx.x * 256 + threadIdx.x;
    if (i >= n4) return;
    float4 v = in[i];
    out[2 * i]     = __floats2half2_rn(v.x, v.y);
    out[2 * i + 1] = __floats2half2_rn(v.z, v.w);
}

// ---------------- embedding (half out) ----------------
__global__ void embed_kernel(const float* __restrict__ x, const float* __restrict__ w,
                             const float* __restrict__ b, __half* __restrict__ h)
{
    int idx = blockIdx.x * 256 + threadIdx.x;
    if (idx >= MTOK * DD) return;
    int row = idx / DD, d = idx % DD;
    int s = row % SS;
    const float* xr = x + row * F_IN;
    float acc = b[d];
    #pragma unroll
    for (int f = 0; f < F_IN; f++) acc += xr[f] * w[f * DD + d];
    acc *= 22.627416997969522f;
    float di2 = (float)(2 * (d >> 1));
    float ang = (float)s * expf(di2 * (-9.210340371976184f / (float)DD));
    float pe = (d & 1) ? cosf(ang) : sinf(ang);
    h[idx] = __float2half_rn(acc + pe);
}

// ---------------- causal softmax: fp32 scores -> half probs ----------------
__global__ void softmax_kernel(const float* __restrict__ s, __half* __restrict__ pr)
{
    int row = blockIdx.x * 8 + (threadIdx.x >> 5);
    if (row >= BB * HH * SS) return;
    int lane = threadIdx.x & 31;
    int q = row % SS;
    const float* p = s + (long long)row * SS;
    __half* o = pr + (long long)row * SS;

    float m = -1e30f;
    for (int j = lane; j <= q; j += 32) m = fmaxf(m, p[j]);
    #pragma unroll
    for (int off = 16; off; off >>= 1) m = fmaxf(m, __shfl_xor_sync(0xffffffffu, m, off));

    float sum = 0.0f;
    for (int j = lane; j <= q; j += 32) sum += expf(p[j] - m);
    #pragma unroll
    for (int off = 16; off; off >>= 1) sum += __shfl_xor_sync(0xffffffffu, sum, off);
    float inv = 1.0f / sum;

    for (int j = lane; j < SS; j += 32)
        o[j] = (j <= q) ? __float2half_rn(expf(p[j] - m) * inv) : __float2half_rn(0.0f);
}

// ---------------- fused residual-add + LayerNorm (fp32 + half -> half) ----------------
__global__ void add_ln_kernel(const float* __restrict__ a, const __half* __restrict__ r,
                              const float* __restrict__ g, const float* __restrict__ bt,
                              __half* __restrict__ o)
{
    int row = blockIdx.x;
    int t = threadIdx.x;
    long long base = (long long)row * DD;
    float x0 = a[base + t]       + __half2float(r[base + t]);
    float x1 = a[base + t + 256] + __half2float(r[base + t + 256]);
    float sm = x0 + x1, sq = x0 * x0 + x1 * x1;
    #pragma unroll
    for (int off = 16; off; off >>= 1) {
        sm += __shfl_xor_sync(0xffffffffu, sm, off);
        sq += __shfl_xor_sync(0xffffffffu, sq, off);
    }
    __shared__ float sh[2][8];
    if ((t & 31) == 0) { sh[0][t >> 5] = sm; sh[1][t >> 5] = sq; }
    __syncthreads();
    float S = 0, Q = 0;
    #pragma unroll
    for (int j = 0; j < 8; j++) { S += sh[0][j]; Q += sh[1][j]; }
    float mean = S * (1.0f / DD);
    float var  = Q * (1.0f / DD) - mean * mean;
    float inv  = rsqrtf(var + 1e-9f);
    o[base + t]       = __float2half_rn((x0 - mean) * inv * g[t]       + bt[t]);
    o[base + t + 256] = __float2half_rn((x1 - mean) * inv * g[t + 256] + bt[t + 256]);
}

// ---------------- final projection ----------------
__global__ void out_kernel(const __half* __restrict__ h, const float* __restrict__ w,
                           const float* __restrict__ b, float* __restrict__ out)
{
    int r = blockIdx.x * 4 + (threadIdx.x >> 5);
    if (r >= BB * NFUT) return;
    int lane = threadIdx.x & 31;
    int bb = r / NFUT, si = r % NFUT;
    const __half* hr = h + ((long long)bb * SS + (SS - NFUT) + si) * DD;
    float acc = 0.0f;
    for (int d = lane; d < DD; d += 32) acc += __half2float(hr[d]) * w[d];
    #pragma unroll
    for (int o = 16; o; o >>= 1) acc += __shfl_xor_sync(0xffffffffu, acc, o);
    if (lane == 0) out[r] = acc + b[0];
}

// ---------------- host-side launcher ----------------
#define FLAG_TRB  1
#define FLAG_BIAS 2
#define FLAG_RELU 4
#define FLAG_OUTH 8

static inline void launch_gemm(const __half* A, const __half* B, const float* bias,
                               float* Cf, __half* Ch,
                               int M, int N, int K, int lda, int ldb, int ldc,
                               long long sAb, long long sAh, long long sBb, long long sBh,
                               long long sCb, long long sCh, int Hs, int Z,
                               float alpha, int flags)
{
    dim3 grid((N + TN - 1) / TN, (M + TM - 1) / TM, Z);
#define LGO(T,Bi,R,H) do { \
        static bool s_set = false; \
        if (!s_set) { cudaFuncSetAttribute(gemm_h<T,Bi,R,H>, cudaFuncAttributeMaxDynamicSharedMemorySize, SMEM_BYTES); s_set = true; } \
        gemm_h<T,Bi,R,H><<<grid, 256, SMEM_BYTES>>>(A, B, bias, Cf, Ch, M, N, K, lda, ldb, ldc, \
            sAb, sAh, sBb, sBh, sCb, sCh, Hs, alpha); } while(0)

    if (flags == (FLAG_BIAS | FLAG_OUTH))                    LGO(false, true,  false, true);
    else if (flags == FLAG_TRB)                              LGO(true,  false, false, false);
    else if (flags == FLAG_OUTH)                             LGO(false, false, false, true);
    else if (flags == FLAG_BIAS)                             LGO(false, true,  false, false);
    else if (flags == (FLAG_BIAS | FLAG_RELU | FLAG_OUTH))   LGO(false, true,  true,  true);
#undef LGO
}

extern "C" void kernel_launch(void* const* d_in, const int* in_sizes, int n_in,
                              void* d_out, int out_size)
{
    const float* x    = (const float*)d_in[0];
    const float* in_w = (const float*)d_in[2];
    const float* in_b = (const float*)d_in[3];
    const float* wq_w = (const float*)d_in[4];
    const float* wq_b = (const float*)d_in[5];
    const float* wk_w = (const float*)d_in[6];
    const float* wk_b = (const float*)d_in[7];
    const float* wv_w = (const float*)d_in[8];
    const float* wv_b = (const float*)d_in[9];
    const float* dn_w = (const float*)d_in[10];
    const float* dn_b = (const float*)d_in[11];
    const float* mh_w = (const float*)d_in[12];
    const float* mh_b = (const float*)d_in[13];
    const float* mo_w = (const float*)d_in[14];
    const float* mo_b = (const float*)d_in[15];
    const float* ln1g = (const float*)d_in[16];
    const float* ln1b = (const float*)d_in[17];
    const float* ln3g = (const float*)d_in[18];
    const float* ln3b = (const float*)d_in[19];
    const float* ow   = (const float*)d_in[20];
    const float* ob   = (const float*)d_in[21];

    __half *h, *h1, *q, *k, *v, *p, *mlp;
    float *t, *sc;
    __half *wqh, *wkh, *wvh, *wdh, *wmhh, *wmoh;
    cudaGetSymbolAddress((void**)&h,    g_h);
    cudaGetSymbolAddress((void**)&h1,   g_h1);
    cudaGetSymbolAddress((void**)&t,    g_t);
    cudaGetSymbolAddress((void**)&q,    g_q);
    cudaGetSymbolAddress((void**)&k,    g_k);
    cudaGetSymbolAddress((void**)&v,    g_v);
    cudaGetSymbolAddress((void**)&sc,   g_s);
    cudaGetSymbolAddress((void**)&p,    g_p);
    cudaGetSymbolAddress((void**)&mlp,  g_mlp);
    cudaGetSymbolAddress((void**)&wqh,  g_wq);
    cudaGetSymbolAddress((void**)&wkh,  g_wk);
    cudaGetSymbolAddress((void**)&wvh,  g_wv);
    cudaGetSymbolAddress((void**)&wdh,  g_wd);
    cudaGetSymbolAddress((void**)&wmhh, g_wmh);
    cudaGetSymbolAddress((void**)&wmoh, g_wmo);

    // convert weights fp32 -> fp16 (once per call; graph-capturable)
    {
        const int n_qkv = LL * DD * DH / 4;
        const int n_mlp = LL * DD * HID / 4;
        f2h_kernel<<<(n_qkv + 255) / 256, 256>>>((const float4*)wq_w, (__half2*)wqh,  n_qkv);
        f2h_kernel<<<(n_qkv + 255) / 256, 256>>>((const float4*)wk_w, (__half2*)wkh,  n_qkv);
        f2h_kernel<<<(n_qkv + 255) / 256, 256>>>((const float4*)wv_w, (__half2*)wvh,  n_qkv);
        f2h_kernel<<<(n_qkv + 255) / 256, 256>>>((const float4*)dn_w, (__half2*)wdh,  n_qkv);
        f2h_kernel<<<(n_mlp + 255) / 256, 256>>>((const float4*)mh_w, (__half2*)wmhh, n_mlp);
        f2h_kernel<<<(n_mlp + 255) / 256, 256>>>((const float4*)mo_w, (__half2*)wmoh, n_mlp);
    }

    const float inv_sqrt_d = 0.044194173824159216f;

    embed_kernel<<<(MTOK * DD + 255) / 256, 256>>>(x, in_w, in_b, h);

    for (int i = 0; i < LL; i++) {
        // QKV (half out)
        launch_gemm(h, wqh + (long long)i * DD * DH, wq_b + (long long)i * DH, nullptr, q,
                    MTOK, DH, DD, DD, DH, DH, 0,0,0,0,0,0, 1, 1, 1.0f, FLAG_BIAS | FLAG_OUTH);
        launch_gemm(h, wkh + (long long)i * DD * DH, wk_b + (long long)i * DH, nullptr, k,
                    MTOK, DH, DD, DD, DH, DH, 0,0,0,0,0,0, 1, 1, 1.0f, FLAG_BIAS | FLAG_OUTH);
        launch_gemm(h, wvh + (long long)i * DD * DH, wv_b + (long long)i * DH, nullptr, v,
                    MTOK, DH, DD, DD, DH, DH, 0,0,0,0,0,0, 1, 1, 1.0f, FLAG_BIAS | FLAG_OUTH);

        // scores = Q @ K^T * inv_sqrt_d (fp32 out), batched over (b,h)
        launch_gemm(q, k, nullptr, sc, nullptr, SS, SS, DD, DH, DH, SS,
                    (long long)SS * DH, DD,
                    (long long)SS * DH, DD,
                    (long long)HH * SS * SS, (long long)SS * SS,
                    HH, BB * HH, inv_sqrt_d, FLAG_TRB);

        softmax_kernel<<<(BB * HH * SS + 7) / 8, 256>>>(sc, p);

        // context = P @ V (half out, reuse q)
        launch_gemm(p, v, nullptr, nullptr, q, SS, DD, SS, SS, DH, DH,
                    (long long)HH * SS * SS, (long long)SS * SS,
                    (long long)SS * DH, DD,
                    (long long)SS * DH, DD,
                    HH, BB * HH, 1.0f, FLAG_OUTH);

        // dn (fp32 out -> LN)
        launch_gemm(q, wdh + (long long)i * DH * DD, dn_b + (long long)i * DD, t, nullptr,
                    MTOK, DD, DH, DH, DD, DD, 0,0,0,0,0,0, 1, 1, 1.0f, FLAG_BIAS);

        add_ln_kernel<<<MTOK, 256>>>(t, h, ln1g + (long long)i * DD, ln1b + (long long)i * DD, h1);

        // MLP up (half out, relu)
        launch_gemm(h1, wmhh + (long long)i * DD * HID, mh_b + (long long)i * HID, nullptr, mlp,
                    MTOK, HID, DD, DD, HID, HID, 0,0,0,0,0,0, 1, 1, 1.0f,
                    FLAG_BIAS | FLAG_RELU | FLAG_OUTH);
        // MLP down (fp32 out -> LN)
        launch_gemm(mlp, wmoh + (long long)i * HID * DD, mo_b + (long long)i * DD, t, nullptr,
                    MTOK, DD, HID, HID, DD, DD, 0,0,0,0,0,0, 1, 1, 1.0f, FLAG_BIAS);

        add_ln_kernel<<<MTOK, 256>>>(t, h1, ln3g + (long long)i * DD, ln3b + (long long)i * DD, h);
    }

    out_kernel<<<(BB * NFUT + 3) / 4, 128>>>(h, ow, ob, (float*)d_out);
}

// round 9
// speedup vs baseline: 8.0621x; 1.0919x over previous
#include <cuda_runtime.h>
#include <cuda_fp16.h>
#include <mma.h>
#include <math.h>

using namespace nvcuda;

// ---------------- problem constants ----------------
#define BB 64
#define SS 168
#define F_IN 10
#define DD 512
#define HH 8
#define LL 4
#define HID 2048
#define NFUT 48
#define DH (DD*HH)          // 4096
#define QKVN (3*DH)         // 12288
#define MTOK (BB*SS)        // 10752

// ---------------- scratch ----------------
__device__ __half g_h   [MTOK*DD];
__device__ __half g_h1  [MTOK*DD];
__device__ float  g_t   [MTOK*DD];        // dn / mo output (fp32 -> LN)
__device__ __half g_qkv [MTOK*QKVN];      // fused QKV output
__device__ __half g_ctx [MTOK*DH];        // attention context
__device__ float  g_s   [BB*HH*SS*SS];    // scores fp32
__device__ __half g_p   [BB*HH*SS*SS];    // probs half
__device__ __half g_mlp [MTOK*HID];
// half weights
__device__ __half g_wqkv[LL*DD*QKVN];     // fused [512,12288] per layer
__device__ float  g_bqkv[LL*QKVN];
__device__ __half g_wd  [LL*DH*DD];
__device__ __half g_wmh [LL*DD*HID];
__device__ __half g_wmo [LL*HID*DD];

// ---------------- cp.async helpers ----------------
__device__ __forceinline__ void cp16(void* dst, const void* src, int bytes) {
    unsigned d = (unsigned)__cvta_generic_to_shared(dst);
    asm volatile("cp.async.cg.shared.global [%0], [%1], 16, %2;\n"
                 :: "r"(d), "l"(src), "r"(bytes));
}
__device__ __forceinline__ void cp16f(void* dst, const void* src) {
    unsigned d = (unsigned)__cvta_generic_to_shared(dst);
    asm volatile("cp.async.cg.shared.global [%0], [%1], 16;\n"
                 :: "r"(d), "l"(src));
}
__device__ __forceinline__ void cp_commit() {
    asm volatile("cp.async.commit_group;\n" ::: "memory");
}
__device__ __forceinline__ void cp_wait1() {
    asm volatile("cp.async.wait_group 1;\n" ::: "memory");
}
__device__ __forceinline__ void cp_wait0() {
    asm volatile("cp.async.wait_group 0;\n" ::: "memory");
}

// ================= templated fp16 GEMM =================
// C = alpha * A[M,K] @ (TRB ? B^T : B) (+bias) (+relu); OUTH: half out else fp32.
// Tiles: TMT x TNT, warps NWM x NWN (each warp (TMT/NWM)x(TNT/NWN)), TK=64.
template<int TMT, int TNT, int NWM, int NWN, int MINB, bool TRB, bool BIAS, bool RELU, bool OUTH>
__global__ void __launch_bounds__(NWM*NWN*32, MINB)
gemm_h(const __half* __restrict__ A, const __half* __restrict__ Bm,
       const float* __restrict__ bias, float* __restrict__ Cf, __half* __restrict__ Ch,
       int M, int N, int K, int lda, int ldb, int ldc,
       long long sAb, long long sAh, long long sBb, long long sBh,
       long long sCb, long long sCh, int Hs, float alpha)
{
    constexpr int THREADS = NWM * NWN * 32;
    constexpr int TKc = 64;
    constexpr int LDA = TKc + 8;                 // 72 halves = 144B (16B-mult)
    constexpr int LDB = TNT + 8;                 // halves (16B-mult)
    constexpr int A_T = TMT * LDA;               // halves
    constexpr int B_T = TRB ? (TNT * LDA) : (TKc * LDB);
    constexpr int STAGE = (A_T + B_T) * 2;       // bytes
    constexpr int WROWS = TMT / NWM, WCOLS = TNT / NWN;
    constexpr int FM = WROWS / 16, FN = WCOLS / 16;
    constexpr int JA = TMT * (TKc / 8) / THREADS;
    constexpr int JB = (TRB ? TNT * (TKc / 8) : TKc * (TNT / 8)) / THREADS;

    extern __shared__ char smraw[];

    const int z = blockIdx.z;
    const int b = z / Hs, hh = z % Hs;
    A  += (long long)b * sAb + (long long)hh * sAh;
    Bm += (long long)b * sBb + (long long)hh * sBh;
    if (OUTH) Ch += (long long)b * sCb + (long long)hh * sCh;
    else      Cf += (long long)b * sCb + (long long)hh * sCh;

    const int tile_m = blockIdx.y * TMT;
    const int tile_n = blockIdx.x * TNT;
    const int tid  = threadIdx.x;
    const int warp = tid >> 5;
    const int lane = tid & 31;
    const int wm = warp % NWM;
    const int wn = warp / NWM;

    wmma::fragment<wmma::accumulator, 16, 16, 16, float> cf[FM][FN];
    #pragma unroll
    for (int i = 0; i < FM; i++)
        #pragma unroll
        for (int j = 0; j < FN; j++)
            wmma::fill_fragment(cf[i][j], 0.0f);

    const int nIter = (K + TKc - 1) / TKc;
    const bool full = (tile_m + TMT <= M) && (tile_n + TNT <= N);
    const bool fast = full && ((K & (TKc - 1)) == 0);

    auto compute = [&](int bufi) {
        const __half* sA = (const __half*)(smraw + bufi * STAGE);
        const __half* sB = sA + A_T;
        #pragma unroll
        for (int kk = 0; kk < TKc; kk += 16) {
            wmma::fragment<wmma::matrix_a, 16, 16, 16, __half, wmma::row_major> af[FM];
            #pragma unroll
            for (int mi = 0; mi < FM; mi++)
                wmma::load_matrix_sync(af[mi], sA + (wm * WROWS + mi * 16) * LDA + kk, LDA);
            if (!TRB) {
                wmma::fragment<wmma::matrix_b, 16, 16, 16, __half, wmma::row_major> bf[FN];
                #pragma unroll
                for (int ni = 0; ni < FN; ni++)
                    wmma::load_matrix_sync(bf[ni], sB + kk * LDB + (wn * WCOLS + ni * 16), LDB);
                #pragma unroll
                for (int mi = 0; mi < FM; mi++)
                    #pragma unroll
                    for (int ni = 0; ni < FN; ni++)
                        wmma::mma_sync(cf[mi][ni], af[mi], bf[ni], cf[mi][ni]);
            } else {
                wmma::fragment<wmma::matrix_b, 16, 16, 16, __half, wmma::col_major> bf[FN];
                #pragma unroll
                for (int ni = 0; ni < FN; ni++)
                    wmma::load_matrix_sync(bf[ni], sB + (wn * WCOLS + ni * 16) * LDA + kk, LDA);
                #pragma unroll
                for (int mi = 0; mi < FM; mi++)
                    #pragma unroll
                    for (int ni = 0; ni < FN; ni++)
                        wmma::mma_sync(cf[mi][ni], af[mi], bf[ni], cf[mi][ni]);
            }
        }
    };

    if (fast) {
        int dA[JA]; const __half* pA[JA];
        int dB[JB]; const __half* pB[JB];
        long long stepB;
        #pragma unroll
        for (int j = 0; j < JA; j++) {
            int c = tid + j * THREADS;
            int r = c >> 3, kc = (c & 7) * 8;
            dA[j] = (r * LDA + kc) * 2;
            pA[j] = A + (long long)(tile_m + r) * lda + kc;
        }
        if (!TRB) {
            #pragma unroll
            for (int j = 0; j < JB; j++) {
                int c = tid + j * THREADS;
                int r = c / (TNT / 8), nc = (c % (TNT / 8)) * 8;
                dB[j] = (A_T + r * LDB + nc) * 2;
                pB[j] = Bm + (long long)r * ldb + tile_n + nc;
            }
            stepB = (long long)TKc * ldb;
        } else {
            #pragma unroll
            for (int j = 0; j < JB; j++) {
                int c = tid + j * THREADS;
                int r = c >> 3, kc = (c & 7) * 8;
                dB[j] = (A_T + r * LDA + kc) * 2;
                pB[j] = Bm + (long long)(tile_n + r) * ldb + kc;
            }
            stepB = TKc;
        }
        auto stageF = [&](int bufi) {
            char* base = smraw + bufi * STAGE;
            #pragma unroll
            for (int j = 0; j < JA; j++) { cp16f(base + dA[j], pA[j]); pA[j] += TKc; }
            #pragma unroll
            for (int j = 0; j < JB; j++) { cp16f(base + dB[j], pB[j]); pB[j] += stepB; }
        };
        stageF(0);
        cp_commit();
        int buf = 0;
        for (int it = 0; it < nIter; ++it) {
            if (it + 1 < nIter) { stageF(buf ^ 1); cp_commit(); cp_wait1(); }
            else cp_wait0();
            __syncthreads();
            compute(buf);
            __syncthreads();
            buf ^= 1;
        }
    } else {
        auto stageS = [&](int it, int bufi) {
            const int k0 = it * TKc;
            __half* sA = (__half*)(smraw + bufi * STAGE);
            __half* sB = sA + A_T;
            #pragma unroll
            for (int j = 0; j < JA; j++) {
                int c = tid + j * THREADS;
                int r = c >> 3, kc = (c & 7) * 8;
                int gm = tile_m + r, gk = k0 + kc;
                int bytes = (gm < M && gk + 8 <= K) ? 16 : 0;
                const __half* src = bytes ? (A + (long long)gm * lda + gk) : A;
                cp16(sA + r * LDA + kc, src, bytes);
            }
            if (!TRB) {
                #pragma unroll
                for (int j = 0; j < JB; j++) {
                    int c = tid + j * THREADS;
                    int r = c / (TNT / 8), nc = (c % (TNT / 8)) * 8;
                    int gk = k0 + r, gn = tile_n + nc;
                    int bytes = (gk < K && gn + 8 <= N) ? 16 : 0;
                    const __half* src = bytes ? (Bm + (long long)gk * ldb + gn) : Bm;
                    cp16(sB + r * LDB + nc, src, bytes);
                }
            } else {
                #pragma unroll
                for (int j = 0; j < JB; j++) {
                    int c = tid + j * THREADS;
                    int r = c >> 3, kc = (c & 7) * 8;
                    int gn = tile_n + r, gk = k0 + kc;
                    int bytes = (gn < N && gk + 8 <= K) ? 16 : 0;
                    const __half* src = bytes ? (Bm + (long long)gn * ldb + gk) : Bm;
                    cp16(sB + r * LDA + kc, src, bytes);
                }
            }
        };
        stageS(0, 0);
        cp_commit();
        int buf = 0;
        for (int it = 0; it < nIter; ++it) {
            if (it + 1 < nIter) { stageS(it + 1, buf ^ 1); cp_commit(); cp_wait1(); }
            else cp_wait0();
            __syncthreads();
            compute(buf);
            __syncthreads();
            buf ^= 1;
        }
    }

    // ---- epilogue: stage fragments through smem (ldm=20 floats = 80B, legal) ----
    float* stg = (float*)smraw + warp * 320;
    #pragma unroll
    for (int mi = 0; mi < FM; mi++) {
        #pragma unroll
        for (int ni = 0; ni < FN; ni++) {
            wmma::store_matrix_sync(stg, cf[mi][ni], 20, wmma::mem_row_major);
            __syncwarp();
            #pragma unroll
            for (int e = lane; e < 256; e += 32) {
                int rr = e >> 4, cc = e & 15;
                int gm = tile_m + wm * WROWS + mi * 16 + rr;
                int gn = tile_n + wn * WCOLS + ni * 16 + cc;
                if (full || (gm < M && gn < N)) {
                    float v = stg[rr * 20 + cc] * alpha;
                    if (BIAS) v += bias[gn];
                    if (RELU) v = fmaxf(v, 0.0f);
                    if (OUTH) Ch[(long long)gm * ldc + gn] = __float2half_rn(v);
                    else      Cf[(long long)gm * ldc + gn] = v;
                }
            }
            __syncwarp();
        }
    }
}

template<int TMT, int TNT, int NWM, int NWN, int MINB, bool TRB, bool BIAS, bool RELU, bool OUTH>
static inline void run_gemm(const __half* A, const __half* B, const float* bias,
                            float* Cf, __half* Ch,
                            int M, int N, int K, int lda, int ldb, int ldc,
                            long long sAb, long long sAh, long long sBb, long long sBh,
                            long long sCb, long long sCh, int Hs, int Z, float alpha)
{
    constexpr int LDA = 72;
    constexpr int A_T = TMT * LDA;
    constexpr int B_T = TRB ? (TNT * LDA) : (64 * (TNT + 8));
    constexpr int SMEM = 2 * ((A_T + B_T) * 2);
    static bool s_init = false;
    if (!s_init) {
        cudaFuncSetAttribute(gemm_h<TMT,TNT,NWM,NWN,MINB,TRB,BIAS,RELU,OUTH>,
                             cudaFuncAttributeMaxDynamicSharedMemorySize, SMEM);
        s_init = true;
    }
    dim3 grid((N + TNT - 1) / TNT, (M + TMT - 1) / TMT, Z);
    gemm_h<TMT,TNT,NWM,NWN,MINB,TRB,BIAS,RELU,OUTH><<<grid, NWM*NWN*32, SMEM>>>(
        A, B, bias, Cf, Ch, M, N, K, lda, ldb, ldc,
        sAb, sAh, sBb, sBh, sCb, sCh, Hs, alpha);
}

// ---------------- weight conversion ----------------
__global__ void f2h_kernel(const float4* __restrict__ in, __half2* __restrict__ out, int n4)
{
    int i = blockIdx.x * 256 + threadIdx.x;
    if (i >= n4) return;
    float4 v = in[i];
    out[2 * i]     = __floats2half2_rn(v.x, v.y);
    out[2 * i + 1] = __floats2half2_rn(v.z, v.w);
}

// fp32 [LL,512,4096] -> half into [LL,512,12288] at column offset `off`
__global__ void f2h_off(const float* __restrict__ src, __half* __restrict__ dst, int off)
{
    long long i = (long long)blockIdx.x * 256 + threadIdx.x;
    const long long tot = (long long)LL * DD * (DH / 2);
    if (i >= tot) return;
    int z   = (int)(i / (DD * (DH / 2)));
    int rem = (int)(i % (DD * (DH / 2)));
    int k = rem / (DH / 2), n2 = rem % (DH / 2);
    float2 v = *(const float2*)(src + (long long)z * DD * DH + (long long)k * DH + n2 * 2);
    *(__half2*)(dst + (long long)z * DD * QKVN + (long long)k * QKVN + off + n2 * 2)
        = __floats2half2_rn(v.x, v.y);
}

__global__ void bias_concat(const float* __restrict__ q, const float* __restrict__ k,
                            const float* __restrict__ v, float* __restrict__ o)
{
    int i = blockIdx.x * 256 + threadIdx.x;
    if (i >= LL * QKVN) return;
    int z = i / QKVN, c = i % QKVN;
    float val = (c < DH) ? q[z * DH + c]
              : (c < 2 * DH) ? k[z * DH + c - DH]
              : v[z * DH + c - 2 * DH];
    o[i] = val;
}

// ---------------- embedding (half out) ----------------
__global__ void embed_kernel(const float* __restrict__ x, const float* __restrict__ w,
                             const float* __restrict__ b, __half* __restrict__ h)
{
    int idx = blockIdx.x * 256 + threadIdx.x;
    if (idx >= MTOK * DD) return;
    int row = idx / DD, d = idx % DD;
    int s = row % SS;
    const float* xr = x + row * F_IN;
    float acc = b[d];
    #pragma unroll
    for (int f = 0; f < F_IN; f++) acc += xr[f] * w[f * DD + d];
    acc *= 22.627416997969522f;
    float di2 = (float)(2 * (d >> 1));
    float ang = (float)s * expf(di2 * (-9.210340371976184f / (float)DD));
    float pe = (d & 1) ? cosf(ang) : sinf(ang);
    h[idx] = __float2half_rn(acc + pe);
}

// ---------------- causal softmax: fp32 scores -> half probs ----------------
__global__ void softmax_kernel(const float* __restrict__ s, __half* __restrict__ pr)
{
    int row = blockIdx.x * 8 + (threadIdx.x >> 5);
    if (row >= BB * HH * SS) return;
    int lane = threadIdx.x & 31;
    int q = row % SS;
    const float* p = s + (long long)row * SS;
    __half* o = pr + (long long)row * SS;

    float m = -1e30f;
    for (int j = lane; j <= q; j += 32) m = fmaxf(m, p[j]);
    #pragma unroll
    for (int off = 16; off; off >>= 1) m = fmaxf(m, __shfl_xor_sync(0xffffffffu, m, off));

    float sum = 0.0f;
    for (int j = lane; j <= q; j += 32) sum += expf(p[j] - m);
    #pragma unroll
    for (int off = 16; off; off >>= 1) sum += __shfl_xor_sync(0xffffffffu, sum, off);
    float inv = 1.0f / sum;

    for (int j = lane; j < SS; j += 32)
        o[j] = (j <= q) ? __float2half_rn(expf(p[j] - m) * inv) : __float2half_rn(0.0f);
}

// ---------------- fused residual-add + LayerNorm (fp32 + half -> half) ----------------
__global__ void add_ln_kernel(const float* __restrict__ a, const __half* __restrict__ r,
                              const float* __restrict__ g, const float* __restrict__ bt,
                              __half* __restrict__ o)
{
    int row = blockIdx.x;
    int t = threadIdx.x;
    long long base = (long long)row * DD;
    float x0 = a[base + t]       + __half2float(r[base + t]);
    float x1 = a[base + t + 256] + __half2float(r[base + t + 256]);
    float sm = x0 + x1, sq = x0 * x0 + x1 * x1;
    #pragma unroll
    for (int off = 16; off; off >>= 1) {
        sm += __shfl_xor_sync(0xffffffffu, sm, off);
        sq += __shfl_xor_sync(0xffffffffu, sq, off);
    }
    __shared__ float sh[2][8];
    if ((t & 31) == 0) { sh[0][t >> 5] = sm; sh[1][t >> 5] = sq; }
    __syncthreads();
    float S = 0, Q = 0;
    #pragma unroll
    for (int j = 0; j < 8; j++) { S += sh[0][j]; Q += sh[1][j]; }
    float mean = S * (1.0f / DD);
    float var  = Q * (1.0f / DD) - mean * mean;
    float inv  = rsqrtf(var + 1e-9f);
    o[base + t]       = __float2half_rn((x0 - mean) * inv * g[t]       + bt[t]);
    o[base + t + 256] = __float2half_rn((x1 - mean) * inv * g[t + 256] + bt[t + 256]);
}

// ---------------- final projection ----------------
__global__ void out_kernel(const __half* __restrict__ h, const float* __restrict__ w,
                           const float* __restrict__ b, float* __restrict__ out)
{
    int r = blockIdx.x * 4 + (threadIdx.x >> 5);
    if (r >= BB * NFUT) return;
    int lane = threadIdx.x & 31;
    int bb = r / NFUT, si = r % NFUT;
    const __half* hr = h + ((long long)bb * SS + (SS - NFUT) + si) * DD;
    float acc = 0.0f;
    for (int d = lane; d < DD; d += 32) acc += __half2float(hr[d]) * w[d];
    #pragma unroll
    for (int o = 16; o; o >>= 1) acc += __shfl_xor_sync(0xffffffffu, acc, o);
    if (lane == 0) out[r] = acc + b[0];
}

extern "C" void kernel_launch(void* const* d_in, const int* in_sizes, int n_in,
                              void* d_out, int out_size)
{
    const float* x    = (const float*)d_in[0];
    const float* in_w = (const float*)d_in[2];
    const float* in_b = (const float*)d_in[3];
    const float* wq_w = (const float*)d_in[4];
    const float* wq_b = (const float*)d_in[5];
    const float* wk_w = (const float*)d_in[6];
    const float* wk_b = (const float*)d_in[7];
    const float* wv_w = (const float*)d_in[8];
    const float* wv_b = (const float*)d_in[9];
    const float* dn_w = (const float*)d_in[10];
    const float* dn_b = (const float*)d_in[11];
    const float* mh_w = (const float*)d_in[12];
    const float* mh_b = (const float*)d_in[13];
    const float* mo_w = (const float*)d_in[14];
    const float* mo_b = (const float*)d_in[15];
    const float* ln1g = (const float*)d_in[16];
    const float* ln1b = (const float*)d_in[17];
    const float* ln3g = (const float*)d_in[18];
    const float* ln3b = (const float*)d_in[19];
    const float* ow   = (const float*)d_in[20];
    const float* ob   = (const float*)d_in[21];

    __half *h, *h1, *qkv, *ctx, *p, *mlp;
    float *t, *sc, *bqkv;
    __half *wqkvh, *wdh, *wmhh, *wmoh;
    cudaGetSymbolAddress((void**)&h,     g_h);
    cudaGetSymbolAddress((void**)&h1,    g_h1);
    cudaGetSymbolAddress((void**)&t,     g_t);
    cudaGetSymbolAddress((void**)&qkv,   g_qkv);
    cudaGetSymbolAddress((void**)&ctx,   g_ctx);
    cudaGetSymbolAddress((void**)&sc,    g_s);
    cudaGetSymbolAddress((void**)&p,     g_p);
    cudaGetSymbolAddress((void**)&mlp,   g_mlp);
    cudaGetSymbolAddress((void**)&wqkvh, g_wqkv);
    cudaGetSymbolAddress((void**)&bqkv,  g_bqkv);
    cudaGetSymbolAddress((void**)&wdh,   g_wd);
    cudaGetSymbolAddress((void**)&wmhh,  g_wmh);
    cudaGetSymbolAddress((void**)&wmoh,  g_wmo);

    // weight conversion (once per call; graph-capturable)
    {
        const long long totq = (long long)LL * DD * (DH / 2);
        const int gq = (int)((totq + 255) / 256);
        f2h_off<<<gq, 256>>>(wq_w, wqkvh, 0);
        f2h_off<<<gq, 256>>>(wk_w, wqkvh, DH);
        f2h_off<<<gq, 256>>>(wv_w, wqkvh, 2 * DH);
        bias_concat<<<(LL * QKVN + 255) / 256, 256>>>(wq_b, wk_b, wv_b, bqkv);
        const int n_qkv = LL * DD * DH / 4;
        const int n_mlp = LL * DD * HID / 4;
        f2h_kernel<<<(n_qkv + 255) / 256, 256>>>((const float4*)dn_w, (__half2*)wdh,  n_qkv);
        f2h_kernel<<<(n_mlp + 255) / 256, 256>>>((const float4*)mh_w, (__half2*)wmhh, n_mlp);
        f2h_kernel<<<(n_mlp + 255) / 256, 256>>>((const float4*)mo_w, (__half2*)wmoh, n_mlp);
    }

    const float inv_sqrt_d = 0.044194173824159216f;

    embed_kernel<<<(MTOK * DD + 255) / 256, 256>>>(x, in_w, in_b, h);

    for (int i = 0; i < LL; i++) {
        // fused QKV: [10752,512] @ [512,12288] (big tile, half out)
        run_gemm<128,128,4,2,2, false,true,false,true>(
            h, wqkvh + (long long)i * DD * QKVN, bqkv + (long long)i * QKVN, nullptr, qkv,
            MTOK, QKVN, DD, DD, QKVN, QKVN, 0,0,0,0,0,0, 1, 1, 1.0f);

        // scores = Q @ K^T * inv_sqrt_d (small tile, TRB, fp32 out)
        run_gemm<64,64,2,2,4, true,false,false,false>(
            qkv, qkv + DH, nullptr, sc, nullptr,
            SS, SS, DD, QKVN, QKVN, SS,
            (long long)SS * QKVN, DD,
            (long long)SS * QKVN, DD,
            (long long)HH * SS * SS, (long long)SS * SS,
            HH, BB * HH, inv_sqrt_d);

        softmax_kernel<<<(BB * HH * SS + 7) / 8, 256>>>(sc, p);

        // context = P @ V (small tile, half out)
        run_gemm<64,64,2,2,4, false,false,false,true>(
            p, qkv + 2 * DH, nullptr, nullptr, ctx,
            SS, DD, SS, SS, QKVN, DH,
            (long long)HH * SS * SS, (long long)SS * SS,
            (long long)SS * QKVN, DD,
            (long long)SS * DH, DD,
            HH, BB * HH, 1.0f);

        // dn (small tile, fp32 out -> LN)
        run_gemm<64,64,2,2,4, false,true,false,false>(
            ctx, wdh + (long long)i * DH * DD, dn_b + (long long)i * DD, t, nullptr,
            MTOK, DD, DH, DH, DD, DD, 0,0,0,0,0,0, 1, 1, 1.0f);

        add_ln_kernel<<<MTOK, 256>>>(t, h, ln1g + (long long)i * DD, ln1b + (long long)i * DD, h1);

        // MLP up (big tile, relu, half out)
        run_gemm<128,128,4,2,2, false,true,true,true>(
            h1, wmhh + (long long)i * DD * HID, mh_b + (long long)i * HID, nullptr, mlp,
            MTOK, HID, DD, DD, HID, HID, 0,0,0,0,0,0, 1, 1, 1.0f);

        // MLP down (small tile, fp32 out -> LN)
        run_gemm<64,64,2,2,4, false,true,false,false>(
            mlp, wmoh + (long long)i * HID * DD, mo_b + (long long)i * DD, t, nullptr,
            MTOK, DD, HID, HID, DD, DD, 0,0,0,0,0,0, 1, 1, 1.0f);

        add_ln_kernel<<<MTOK, 256>>>(t, h1, ln3g + (long long)i * DD, ln3b + (long long)i * DD, h);
    }

    out_kernel<<<(BB * NFUT + 3) / 4, 128>>>(h, ow, ob, (float*)d_out);
}